// round 1
// baseline (speedup 1.0000x reference)
#include <cuda_runtime.h>
#include <cstddef>

// Problem constants
// B=32, T=64 -> BT=2048; NE=64 entities; NA=16 agents; ED=128; E=512; H=8; HD=64; R=512
#define BT_   2048
#define M_X1  131072          // BT*NE
#define M_AG  32768           // BT*NA

// Scratch (device globals; no allocation allowed)
__device__ float g_x1  [(size_t)M_X1 * 512];    // 256 MB: relu(x@W1^T + b1)
__device__ float g_kv  [(size_t)M_X1 * 1024];   // 512 MB: [k | v]
__device__ float g_q   [(size_t)M_AG * 512];    //  64 MB
__device__ float g_attn[(size_t)M_AG * 512];    //  64 MB
__device__ float g_h   [(size_t)M_AG * 512];    //  64 MB: relu(masked(attn@Wout+b))

// ---------------------------------------------------------------------------
// Generic NT SGEMM: C[M,N] = epilogue( A[M,K] * B[N,K]^T + bias )
//   flags bit0: relu
//   flags bit1: zero rows where emask[(row>>4)*64 + (row&15)] != 0  (agent mask)
//   flags bit2: gather A rows: arow = (row>>4)*64 + (row&15)        (agent gather)
// Tile 128x128, K-chunk 16, 256 threads, 8x8 per thread.
// ---------------------------------------------------------------------------
__global__ __launch_bounds__(256) void sgemm_nt(
    const float* __restrict__ A, const float* __restrict__ B, float* __restrict__ C,
    int M, int N, int K,
    const float* __restrict__ bias,
    const unsigned* __restrict__ emask,
    int flags)
{
    __shared__ float As[16][128];
    __shared__ float Bs[16][128];

    const int tid = threadIdx.x;
    const int bm = blockIdx.y * 128;
    const int bn = blockIdx.x * 128;
    const int ty = tid >> 4;          // 0..15
    const int tx = tid & 15;          // 0..15

    float acc[8][8];
    #pragma unroll
    for (int i = 0; i < 8; i++)
        #pragma unroll
        for (int j = 0; j < 8; j++) acc[i][j] = 0.f;

    const int lrow = tid >> 1;        // 0..127
    const int lcol = (tid & 1) * 8;   // 0 or 8
    const int grow = bm + lrow;
    const int arow = (flags & 4) ? ((grow >> 4) * 64 + (grow & 15)) : grow;
    const float* Aptr = A + (size_t)arow * K + lcol;
    const float* Bptr = B + (size_t)(bn + lrow) * K + lcol;

    for (int k0 = 0; k0 < K; k0 += 16) {
        float4 a0 = *(const float4*)(Aptr + k0);
        float4 a1 = *(const float4*)(Aptr + k0 + 4);
        float4 b0 = *(const float4*)(Bptr + k0);
        float4 b1 = *(const float4*)(Bptr + k0 + 4);

        As[lcol + 0][lrow] = a0.x; As[lcol + 1][lrow] = a0.y;
        As[lcol + 2][lrow] = a0.z; As[lcol + 3][lrow] = a0.w;
        As[lcol + 4][lrow] = a1.x; As[lcol + 5][lrow] = a1.y;
        As[lcol + 6][lrow] = a1.z; As[lcol + 7][lrow] = a1.w;

        Bs[lcol + 0][lrow] = b0.x; Bs[lcol + 1][lrow] = b0.y;
        Bs[lcol + 2][lrow] = b0.z; Bs[lcol + 3][lrow] = b0.w;
        Bs[lcol + 4][lrow] = b1.x; Bs[lcol + 5][lrow] = b1.y;
        Bs[lcol + 6][lrow] = b1.z; Bs[lcol + 7][lrow] = b1.w;

        __syncthreads();

        #pragma unroll
        for (int kk = 0; kk < 16; ++kk) {
            float a[8], b[8];
            *(float4*)(a)     = *(const float4*)&As[kk][ty * 8];
            *(float4*)(a + 4) = *(const float4*)&As[kk][ty * 8 + 4];
            *(float4*)(b)     = *(const float4*)&Bs[kk][tx * 8];
            *(float4*)(b + 4) = *(const float4*)&Bs[kk][tx * 8 + 4];
            #pragma unroll
            for (int i = 0; i < 8; i++)
                #pragma unroll
                for (int j = 0; j < 8; j++)
                    acc[i][j] += a[i] * b[j];
        }
        __syncthreads();
    }

    // epilogue
    float bv[8];
    #pragma unroll
    for (int j = 0; j < 8; j++)
        bv[j] = bias ? bias[bn + tx * 8 + j] : 0.f;

    #pragma unroll
    for (int i = 0; i < 8; i++) {
        int row = bm + ty * 8 + i;
        bool zero = false;
        if (flags & 2) {
            int ent = (row >> 4) * 64 + (row & 15);
            zero = (emask[ent] != 0u);
        }
        float o[8];
        #pragma unroll
        for (int j = 0; j < 8; j++) {
            float v = acc[i][j] + bv[j];
            if (flags & 1) v = fmaxf(v, 0.f);
            if (zero) v = 0.f;
            o[j] = v;
        }
        float* cp = C + (size_t)row * N + bn + tx * 8;
        *(float4*)(cp)     = *(const float4*)(o);
        *(float4*)(cp + 4) = *(const float4*)(o + 4);
    }
}

// ---------------------------------------------------------------------------
// Attention: one block per (head, bt). 128 threads.
// q: [BT*NA, 512] (cols h*64+d)   kv: [BT*NE, 1024] (k = cols 0..511, v = 512..1023)
// obs: [BT, 64, 64] nonzero => masked (NEG)
// attn out: [BT*NA, 512]
// ---------------------------------------------------------------------------
__global__ __launch_bounds__(128) void attn_kernel(
    const float* __restrict__ q, const float* __restrict__ kv,
    const unsigned* __restrict__ obs, float* __restrict__ attn)
{
    const int h = blockIdx.x;
    const int bt = blockIdx.y;
    const int t = threadIdx.x;

    __shared__ float qs[16][64];
    __shared__ float ks[64][65];
    __shared__ float vs[64][65];
    __shared__ float ls[16][64];

    #pragma unroll
    for (int i = 0; i < 8; i++) {
        int idx = i * 128 + t;                 // 0..1023
        int a = idx >> 6, d = idx & 63;
        qs[a][d] = q[(size_t)(bt * 16 + a) * 512 + h * 64 + d];
    }
    #pragma unroll
    for (int i = 0; i < 32; i++) {
        int idx = i * 128 + t;                 // 0..4095
        int e = idx >> 6, d = idx & 63;
        const float* base = kv + (size_t)(bt * 64 + e) * 1024 + h * 64 + d;
        ks[e][d] = base[0];
        vs[e][d] = base[512];
    }
    __syncthreads();

    // logits (scaled + masked)
    #pragma unroll
    for (int i = 0; i < 8; i++) {
        int idx = i * 128 + t;
        int a = idx >> 6, e = idx & 63;
        float s = 0.f;
        #pragma unroll
        for (int d = 0; d < 64; d++) s += qs[a][d] * ks[e][d];
        s *= 0.125f;                           // 1/sqrt(64)
        if (obs[(size_t)bt * 4096 + a * 64 + e] != 0u) s = -1e30f;
        ls[a][e] = s;
    }
    __syncthreads();

    // softmax: warp w handles rows 4w..4w+3, lane covers e = {lane, lane+32}
    const int warp = t >> 5, lane = t & 31;
    #pragma unroll
    for (int r = 0; r < 4; r++) {
        int a = warp * 4 + r;
        float x0 = ls[a][lane], x1 = ls[a][lane + 32];
        float mx = fmaxf(x0, x1);
        #pragma unroll
        for (int o = 16; o; o >>= 1) mx = fmaxf(mx, __shfl_xor_sync(0xffffffffu, mx, o));
        float e0 = __expf(x0 - mx), e1 = __expf(x1 - mx);
        float sm = e0 + e1;
        #pragma unroll
        for (int o = 16; o; o >>= 1) sm += __shfl_xor_sync(0xffffffffu, sm, o);
        float inv = (mx <= -1e29f) ? 0.f : (1.f / sm);   // all_masked -> w = 0
        ls[a][lane] = e0 * inv;
        ls[a][lane + 32] = e1 * inv;
    }
    __syncthreads();

    // attn[a][d] = sum_e w[a][e] * v[e][d]
    #pragma unroll
    for (int i = 0; i < 8; i++) {
        int idx = i * 128 + t;
        int a = idx >> 6, d = idx & 63;
        float s = 0.f;
        #pragma unroll
        for (int e = 0; e < 64; e++) s += ls[a][e] * vs[e][d];
        attn[(size_t)(bt * 16 + a) * 512 + h * 64 + d] = s;
    }
}

// ---------------------------------------------------------------------------
extern "C" void kernel_launch(void* const* d_in, const int* in_sizes, int n_in,
                              void* d_out, int out_size)
{
    (void)in_sizes; (void)n_in; (void)out_size;
    const float*    entities    = (const float*)d_in[0];
    const unsigned* obs_mask    = (const unsigned*)d_in[1];   // bool canonicalized to 4-byte 0/1
    const unsigned* entity_mask = (const unsigned*)d_in[2];
    const float*    W1    = (const float*)d_in[3];
    const float*    b1    = (const float*)d_in[4];
    const float*    Win   = (const float*)d_in[5];
    const float*    Wout  = (const float*)d_in[6];
    const float*    b_out = (const float*)d_in[7];
    const float*    W2    = (const float*)d_in[8];
    const float*    b2    = (const float*)d_in[9];
    float* out = (float*)d_out;

    float *x1, *kvp, *qp, *attnp, *hp;
    cudaGetSymbolAddress((void**)&x1,    g_x1);
    cudaGetSymbolAddress((void**)&kvp,   g_kv);
    cudaGetSymbolAddress((void**)&qp,    g_q);
    cudaGetSymbolAddress((void**)&attnp, g_attn);
    cudaGetSymbolAddress((void**)&hp,    g_h);

    // 1) x1 = relu(entities @ W1^T + b1)        [131072, 512]
    sgemm_nt<<<dim3(512 / 128, M_X1 / 128), 256>>>(
        entities, W1, x1, M_X1, 512, 128, b1, nullptr, /*relu*/1);

    // 2) kv = x1 @ Win[512:1536]^T              [131072, 1024]
    sgemm_nt<<<dim3(1024 / 128, M_X1 / 128), 256>>>(
        x1, Win + (size_t)512 * 512, kvp, M_X1, 1024, 512, nullptr, nullptr, 0);

    // 3) q = x1[agent rows] @ Win[0:512]^T      [32768, 512]
    sgemm_nt<<<dim3(512 / 128, M_AG / 128), 256>>>(
        x1, Win, qp, M_AG, 512, 512, nullptr, nullptr, /*gather*/4);

    // 4) masked multi-head attention -> attn    [32768, 512]
    attn_kernel<<<dim3(8, BT_), 128>>>(qp, kvp, obs_mask, attnp);

    // 5) h = agent_mask ? 0 : relu(attn @ Wout^T + b_out)
    sgemm_nt<<<dim3(512 / 128, M_AG / 128), 256>>>(
        attnp, Wout, hp, M_AG, 512, 512, b_out, entity_mask, /*relu|mask*/3);

    // 6) out = relu(h @ W2^T + b2)              [32768, 512]
    sgemm_nt<<<dim3(512 / 128, M_AG / 128), 256>>>(
        hp, W2, out, M_AG, 512, 512, b2, nullptr, /*relu*/1);
}

// round 2
// speedup vs baseline: 1.4980x; 1.4980x over previous
#include <cuda_runtime.h>
#include <cstdint>
#include <cstddef>

// B=32, T=64 -> BT=2048; NE=64; NA=16; ED=128; E=512; H=8; HD=64; R=512
#define BT_   2048
#define M_X1  131072          // BT*NE
#define M_AG  32768           // BT*NA

__device__ float g_x1  [(size_t)M_X1 * 512];
__device__ float g_kv  [(size_t)M_X1 * 1024];
__device__ float g_q   [(size_t)M_AG * 512];
__device__ float g_attn[(size_t)M_AG * 512];
__device__ float g_h   [(size_t)M_AG * 512];

// ---------------------------------------------------------------------------
// tf32 x3 helpers
// ---------------------------------------------------------------------------
__device__ __forceinline__ void f32split(float x, uint32_t& hi, uint32_t& lo) {
    unsigned u = __float_as_uint(x);
    unsigned h = u & 0xFFFFE000u;          // keep 10 mantissa bits (tf32)
    hi = h;
    lo = __float_as_uint(x - __uint_as_float(h));
}

__device__ __forceinline__ void mma8(float* d, const uint32_t* a, const uint32_t* b) {
    asm volatile(
        "mma.sync.aligned.m16n8k8.row.col.f32.tf32.tf32.f32 "
        "{%0,%1,%2,%3},{%4,%5,%6,%7},{%8,%9},{%0,%1,%2,%3};\n"
        : "+f"(d[0]), "+f"(d[1]), "+f"(d[2]), "+f"(d[3])
        : "r"(a[0]), "r"(a[1]), "r"(a[2]), "r"(a[3]), "r"(b[0]), "r"(b[1]));
}

// ---------------------------------------------------------------------------
// NT GEMM with tf32x3 tensor-core path.
// C[M,N] = epi( A[M,K] * B[N,K]^T + bias )
//   flags bit0: relu
//   flags bit1: zero rows where emask[(row>>4)*64 + (row&15)] != 0
//   flags bit2: gather A rows: arow = (row>>4)*64 + (row&15)
// Block tile 128x128, K-chunk 32, 256 threads (8 warps: 4 in M x 2 in N).
// Warp tile 32(M) x 64(N): 2 m-frags x 8 n-frags of m16n8k8.
// ---------------------------------------------------------------------------
__global__ __launch_bounds__(256, 2) void gemm_tf32x3(
    const float* __restrict__ A, const float* __restrict__ B, float* __restrict__ C,
    int M, int N, int K,
    const float* __restrict__ bias,
    const unsigned* __restrict__ emask,
    int flags)
{
    __shared__ float As[128][36];   // padded: stride 36 -> conflict-free frag loads
    __shared__ float Bs[128][36];

    const int tid  = threadIdx.x;
    const int warp = tid >> 5;
    const int lane = tid & 31;
    const int wm   = warp >> 1;         // 0..3 -> M offset 32*wm
    const int wn   = warp & 1;          // 0..1 -> N offset 64*wn
    const int gid  = lane >> 2;         // 0..7
    const int tig  = lane & 3;          // 0..3

    const int bm = blockIdx.y * 128;
    const int bn = blockIdx.x * 128;

    float acc[2][8][4];
    #pragma unroll
    for (int i = 0; i < 2; i++)
        #pragma unroll
        for (int j = 0; j < 8; j++)
            #pragma unroll
            for (int t = 0; t < 4; t++) acc[i][j][t] = 0.f;

    // global->smem: each thread loads 4 float4 of A and 4 float4 of B
    const int lr = tid >> 1;            // 0..127
    const int lc = (tid & 1) * 16;      // 0 or 16
    const int grow = bm + lr;
    const int arow = (flags & 4) ? ((grow >> 4) * 64 + (grow & 15)) : grow;
    const float* Ap = A + (size_t)arow * K + lc;
    const float* Bp = B + (size_t)(bn + lr) * K + lc;

    for (int k0 = 0; k0 < K; k0 += 32) {
        #pragma unroll
        for (int j = 0; j < 4; j++) {
            float4 av = *(const float4*)(Ap + k0 + j * 4);
            float4 bv = *(const float4*)(Bp + k0 + j * 4);
            *(float4*)&As[lr][lc + j * 4] = av;
            *(float4*)&Bs[lr][lc + j * 4] = bv;
        }
        __syncthreads();

        #pragma unroll
        for (int kk = 0; kk < 32; kk += 8) {
            // A fragments (hi/lo) for the 2 m-frags
            uint32_t ah[2][4], al[2][4];
            #pragma unroll
            for (int mf = 0; mf < 2; mf++) {
                int r0 = wm * 32 + mf * 16 + gid;
                f32split(As[r0    ][kk + tig    ], ah[mf][0], al[mf][0]);
                f32split(As[r0 + 8][kk + tig    ], ah[mf][1], al[mf][1]);
                f32split(As[r0    ][kk + tig + 4], ah[mf][2], al[mf][2]);
                f32split(As[r0 + 8][kk + tig + 4], ah[mf][3], al[mf][3]);
            }
            #pragma unroll
            for (int nf = 0; nf < 8; nf++) {
                int c0 = wn * 64 + nf * 8 + gid;
                uint32_t bh[2], bl[2];
                f32split(Bs[c0][kk + tig    ], bh[0], bl[0]);
                f32split(Bs[c0][kk + tig + 4], bh[1], bl[1]);
                #pragma unroll
                for (int mf = 0; mf < 2; mf++) {
                    mma8(acc[mf][nf], al[mf], bh);   // lo*hi
                    mma8(acc[mf][nf], ah[mf], bl);   // hi*lo
                    mma8(acc[mf][nf], ah[mf], bh);   // hi*hi
                }
            }
        }
        __syncthreads();
    }

    // epilogue
    #pragma unroll
    for (int mf = 0; mf < 2; mf++) {
        int r0 = bm + wm * 32 + mf * 16 + gid;      // rows r0 and r0+8
        bool z0 = false, z1 = false;
        if (flags & 2) {
            int e0 = ((r0    ) >> 4) * 64 + ((r0    ) & 15);
            int e1 = ((r0 + 8) >> 4) * 64 + ((r0 + 8) & 15);
            z0 = (emask[e0] != 0u);
            z1 = (emask[e1] != 0u);
        }
        #pragma unroll
        for (int nf = 0; nf < 8; nf++) {
            int c = bn + wn * 64 + nf * 8 + tig * 2;
            float b0 = bias ? bias[c]     : 0.f;
            float b1 = bias ? bias[c + 1] : 0.f;
            float v0 = acc[mf][nf][0] + b0;
            float v1 = acc[mf][nf][1] + b1;
            float v2 = acc[mf][nf][2] + b0;
            float v3 = acc[mf][nf][3] + b1;
            if (flags & 1) {
                v0 = fmaxf(v0, 0.f); v1 = fmaxf(v1, 0.f);
                v2 = fmaxf(v2, 0.f); v3 = fmaxf(v3, 0.f);
            }
            if (z0) { v0 = 0.f; v1 = 0.f; }
            if (z1) { v2 = 0.f; v3 = 0.f; }
            *(float2*)(C + (size_t)r0 * N + c)       = make_float2(v0, v1);
            *(float2*)(C + (size_t)(r0 + 8) * N + c) = make_float2(v2, v3);
        }
    }
}

// ---------------------------------------------------------------------------
// Attention: one block per (head, bt). 128 threads. (unchanged from R1)
// ---------------------------------------------------------------------------
__global__ __launch_bounds__(128) void attn_kernel(
    const float* __restrict__ q, const float* __restrict__ kv,
    const unsigned* __restrict__ obs, float* __restrict__ attn)
{
    const int h = blockIdx.x;
    const int bt = blockIdx.y;
    const int t = threadIdx.x;

    __shared__ float qs[16][64];
    __shared__ float ks[64][65];
    __shared__ float vs[64][65];
    __shared__ float ls[16][64];

    #pragma unroll
    for (int i = 0; i < 8; i++) {
        int idx = i * 128 + t;
        int a = idx >> 6, d = idx & 63;
        qs[a][d] = q[(size_t)(bt * 16 + a) * 512 + h * 64 + d];
    }
    #pragma unroll
    for (int i = 0; i < 32; i++) {
        int idx = i * 128 + t;
        int e = idx >> 6, d = idx & 63;
        const float* base = kv + (size_t)(bt * 64 + e) * 1024 + h * 64 + d;
        ks[e][d] = base[0];
        vs[e][d] = base[512];
    }
    __syncthreads();

    #pragma unroll
    for (int i = 0; i < 8; i++) {
        int idx = i * 128 + t;
        int a = idx >> 6, e = idx & 63;
        float s = 0.f;
        #pragma unroll
        for (int d = 0; d < 64; d++) s += qs[a][d] * ks[e][d];
        s *= 0.125f;
        if (obs[(size_t)bt * 4096 + a * 64 + e] != 0u) s = -1e30f;
        ls[a][e] = s;
    }
    __syncthreads();

    const int warp = t >> 5, lane = t & 31;
    #pragma unroll
    for (int r = 0; r < 4; r++) {
        int a = warp * 4 + r;
        float x0 = ls[a][lane], x1 = ls[a][lane + 32];
        float mx = fmaxf(x0, x1);
        #pragma unroll
        for (int o = 16; o; o >>= 1) mx = fmaxf(mx, __shfl_xor_sync(0xffffffffu, mx, o));
        float e0 = __expf(x0 - mx), e1 = __expf(x1 - mx);
        float sm = e0 + e1;
        #pragma unroll
        for (int o = 16; o; o >>= 1) sm += __shfl_xor_sync(0xffffffffu, sm, o);
        float inv = (mx <= -1e29f) ? 0.f : (1.f / sm);
        ls[a][lane] = e0 * inv;
        ls[a][lane + 32] = e1 * inv;
    }
    __syncthreads();

    #pragma unroll
    for (int i = 0; i < 8; i++) {
        int idx = i * 128 + t;
        int a = idx >> 6, d = idx & 63;
        float s = 0.f;
        #pragma unroll
        for (int e = 0; e < 64; e++) s += ls[a][e] * vs[e][d];
        attn[(size_t)(bt * 16 + a) * 512 + h * 64 + d] = s;
    }
}

// ---------------------------------------------------------------------------
extern "C" void kernel_launch(void* const* d_in, const int* in_sizes, int n_in,
                              void* d_out, int out_size)
{
    (void)in_sizes; (void)n_in; (void)out_size;
    const float*    entities    = (const float*)d_in[0];
    const unsigned* obs_mask    = (const unsigned*)d_in[1];
    const unsigned* entity_mask = (const unsigned*)d_in[2];
    const float*    W1    = (const float*)d_in[3];
    const float*    b1    = (const float*)d_in[4];
    const float*    Win   = (const float*)d_in[5];
    const float*    Wout  = (const float*)d_in[6];
    const float*    b_out = (const float*)d_in[7];
    const float*    W2    = (const float*)d_in[8];
    const float*    b2    = (const float*)d_in[9];
    float* out = (float*)d_out;

    float *x1, *kvp, *qp, *attnp, *hp;
    cudaGetSymbolAddress((void**)&x1,    g_x1);
    cudaGetSymbolAddress((void**)&kvp,   g_kv);
    cudaGetSymbolAddress((void**)&qp,    g_q);
    cudaGetSymbolAddress((void**)&attnp, g_attn);
    cudaGetSymbolAddress((void**)&hp,    g_h);

    // 1) x1 = relu(entities @ W1^T + b1)        [131072, 512], K=128
    gemm_tf32x3<<<dim3(512 / 128, M_X1 / 128), 256>>>(
        entities, W1, x1, M_X1, 512, 128, b1, nullptr, 1);

    // 2) kv = x1 @ Win[512:1536]^T              [131072, 1024], K=512
    gemm_tf32x3<<<dim3(1024 / 128, M_X1 / 128), 256>>>(
        x1, Win + (size_t)512 * 512, kvp, M_X1, 1024, 512, nullptr, nullptr, 0);

    // 3) q = x1[agent rows] @ Win[0:512]^T      [32768, 512], K=512
    gemm_tf32x3<<<dim3(512 / 128, M_AG / 128), 256>>>(
        x1, Win, qp, M_AG, 512, 512, nullptr, nullptr, 4);

    // 4) masked multi-head attention
    attn_kernel<<<dim3(8, BT_), 128>>>(qp, kvp, obs_mask, attnp);

    // 5) h = agent_mask ? 0 : relu(attn @ Wout^T + b_out)
    gemm_tf32x3<<<dim3(512 / 128, M_AG / 128), 256>>>(
        attnp, Wout, hp, M_AG, 512, 512, b_out, entity_mask, 3);

    // 6) out = relu(h @ W2^T + b2)
    gemm_tf32x3<<<dim3(512 / 128, M_AG / 128), 256>>>(
        hp, W2, out, M_AG, 512, 512, b2, nullptr, 1);
}

// round 3
// speedup vs baseline: 1.9222x; 1.2832x over previous
#include <cuda_runtime.h>
#include <cuda_fp16.h>
#include <cstdint>
#include <cstddef>

// B=32, T=64 -> BT=2048; NE=64; NA=16; ED=128; E=512; H=8; HD=64; R=512
#define BT_   2048
#define M_X1  131072          // BT*NE
#define M_AG  32768           // BT*NA

__device__ float g_x1  [(size_t)M_X1 * 512];
__device__ float g_kv  [(size_t)M_X1 * 1024];
__device__ float g_q   [(size_t)M_AG * 512];
__device__ float g_attn[(size_t)M_AG * 512];
__device__ float g_h   [(size_t)M_AG * 512];

// ---------------------------------------------------------------------------
__device__ __forceinline__ void mma16(float* d, const uint32_t* a, const uint32_t* b) {
    asm volatile(
        "mma.sync.aligned.m16n8k16.row.col.f32.f16.f16.f32 "
        "{%0,%1,%2,%3},{%4,%5,%6,%7},{%8,%9},{%0,%1,%2,%3};\n"
        : "+f"(d[0]), "+f"(d[1]), "+f"(d[2]), "+f"(d[3])
        : "r"(a[0]), "r"(a[1]), "r"(a[2]), "r"(a[3]), "r"(b[0]), "r"(b[1]));
}

__device__ __forceinline__ uint32_t lds32(const __half* p) {
    return *reinterpret_cast<const uint32_t*>(p);
}

// split a float4 into hi/lo half2 pairs and store 4 halves to each array
__device__ __forceinline__ void split_store4(__half* hi, __half* lo, float4 v) {
    half2 h01 = __floats2half2_rn(v.x, v.y);
    half2 h23 = __floats2half2_rn(v.z, v.w);
    float2 f01 = __half22float2(h01);
    float2 f23 = __half22float2(h23);
    half2 l01 = __floats2half2_rn(v.x - f01.x, v.y - f01.y);
    half2 l23 = __floats2half2_rn(v.z - f23.x, v.w - f23.y);
    *reinterpret_cast<half2*>(hi)     = h01;
    *reinterpret_cast<half2*>(hi + 2) = h23;
    *reinterpret_cast<half2*>(lo)     = l01;
    *reinterpret_cast<half2*>(lo + 2) = l23;
}

// ---------------------------------------------------------------------------
// NT GEMM, fp16x3 error-compensated tensor-core path.
// C[M,N] = epi( A[M,K] * B[N,K]^T + bias )
//   flags bit0: relu
//   flags bit1: zero rows where emask[(row>>4)*64 + (row&15)] != 0
//   flags bit2: gather A rows: arow = (row>>4)*64 + (row&15)
// Block tile 128x128, K-chunk 32, 256 threads (8 warps: 4M x 2N).
// Warp tile 32(M) x 64(N): 2 m-frags x 8 n-frags of m16n8k16.
// ---------------------------------------------------------------------------
#define SPAD 40   // half-elements per smem row (80B): conflict-free (20*gid+tig distinct)

__global__ __launch_bounds__(256, 2) void gemm_f16x3(
    const float* __restrict__ A, const float* __restrict__ B, float* __restrict__ C,
    int M, int N, int K,
    const float* __restrict__ bias,
    const unsigned* __restrict__ emask,
    int flags)
{
    __shared__ __half As_hi[128][SPAD];
    __shared__ __half As_lo[128][SPAD];
    __shared__ __half Bs_hi[128][SPAD];
    __shared__ __half Bs_lo[128][SPAD];

    const int tid  = threadIdx.x;
    const int warp = tid >> 5;
    const int lane = tid & 31;
    const int wm   = warp >> 1;         // 0..3
    const int wn   = warp & 1;          // 0..1
    const int gid  = lane >> 2;         // 0..7
    const int tig  = lane & 3;          // 0..3

    const int bm = blockIdx.y * 128;
    const int bn = blockIdx.x * 128;

    float acc[2][8][4];
    #pragma unroll
    for (int i = 0; i < 2; i++)
        #pragma unroll
        for (int j = 0; j < 8; j++)
            #pragma unroll
            for (int t = 0; t < 4; t++) acc[i][j][t] = 0.f;

    // global->smem staging: each thread covers 16 contiguous K of one row (A and B)
    const int lr = tid >> 1;            // 0..127
    const int lc = (tid & 1) * 16;      // 0 or 16
    const int grow = bm + lr;
    const int arow = (flags & 4) ? ((grow >> 4) * 64 + (grow & 15)) : grow;
    const float* Ap = A + (size_t)arow * K + lc;
    const float* Bp = B + (size_t)(bn + lr) * K + lc;

    for (int k0 = 0; k0 < K; k0 += 32) {
        #pragma unroll
        for (int j = 0; j < 4; j++) {
            float4 av = *(const float4*)(Ap + k0 + j * 4);
            float4 bv = *(const float4*)(Bp + k0 + j * 4);
            split_store4(&As_hi[lr][lc + j * 4], &As_lo[lr][lc + j * 4], av);
            split_store4(&Bs_hi[lr][lc + j * 4], &Bs_lo[lr][lc + j * 4], bv);
        }
        __syncthreads();

        #pragma unroll
        for (int kk = 0; kk < 32; kk += 16) {
            const int ka = kk + 2 * tig;
            uint32_t ah[2][4], al[2][4];
            #pragma unroll
            for (int mf = 0; mf < 2; mf++) {
                int r0 = wm * 32 + mf * 16 + gid;
                ah[mf][0] = lds32(&As_hi[r0    ][ka    ]);
                ah[mf][1] = lds32(&As_hi[r0 + 8][ka    ]);
                ah[mf][2] = lds32(&As_hi[r0    ][ka + 8]);
                ah[mf][3] = lds32(&As_hi[r0 + 8][ka + 8]);
                al[mf][0] = lds32(&As_lo[r0    ][ka    ]);
                al[mf][1] = lds32(&As_lo[r0 + 8][ka    ]);
                al[mf][2] = lds32(&As_lo[r0    ][ka + 8]);
                al[mf][3] = lds32(&As_lo[r0 + 8][ka + 8]);
            }
            #pragma unroll
            for (int nf = 0; nf < 8; nf++) {
                int c0 = wn * 64 + nf * 8 + gid;
                uint32_t bh[2], bl[2];
                bh[0] = lds32(&Bs_hi[c0][ka    ]);
                bh[1] = lds32(&Bs_hi[c0][ka + 8]);
                bl[0] = lds32(&Bs_lo[c0][ka    ]);
                bl[1] = lds32(&Bs_lo[c0][ka + 8]);
                #pragma unroll
                for (int mf = 0; mf < 2; mf++) {
                    mma16(acc[mf][nf], al[mf], bh);   // lo*hi
                    mma16(acc[mf][nf], ah[mf], bl);   // hi*lo
                    mma16(acc[mf][nf], ah[mf], bh);   // hi*hi
                }
            }
        }
        __syncthreads();
    }

    // epilogue
    #pragma unroll
    for (int mf = 0; mf < 2; mf++) {
        int r0 = bm + wm * 32 + mf * 16 + gid;      // rows r0 and r0+8
        bool z0 = false, z1 = false;
        if (flags & 2) {
            int e0 = ((r0    ) >> 4) * 64 + ((r0    ) & 15);
            int e1 = ((r0 + 8) >> 4) * 64 + ((r0 + 8) & 15);
            z0 = (emask[e0] != 0u);
            z1 = (emask[e1] != 0u);
        }
        #pragma unroll
        for (int nf = 0; nf < 8; nf++) {
            int c = bn + wn * 64 + nf * 8 + tig * 2;
            float b0 = bias ? bias[c]     : 0.f;
            float b1 = bias ? bias[c + 1] : 0.f;
            float v0 = acc[mf][nf][0] + b0;
            float v1 = acc[mf][nf][1] + b1;
            float v2 = acc[mf][nf][2] + b0;
            float v3 = acc[mf][nf][3] + b1;
            if (flags & 1) {
                v0 = fmaxf(v0, 0.f); v1 = fmaxf(v1, 0.f);
                v2 = fmaxf(v2, 0.f); v3 = fmaxf(v3, 0.f);
            }
            if (z0) { v0 = 0.f; v1 = 0.f; }
            if (z1) { v2 = 0.f; v3 = 0.f; }
            *(float2*)(C + (size_t)r0 * N + c)       = make_float2(v0, v1);
            *(float2*)(C + (size_t)(r0 + 8) * N + c) = make_float2(v2, v3);
        }
    }
}

// ---------------------------------------------------------------------------
// Attention: one block per (head, bt). 128 threads. (unchanged)
// ---------------------------------------------------------------------------
__global__ __launch_bounds__(128) void attn_kernel(
    const float* __restrict__ q, const float* __restrict__ kv,
    const unsigned* __restrict__ obs, float* __restrict__ attn)
{
    const int h = blockIdx.x;
    const int bt = blockIdx.y;
    const int t = threadIdx.x;

    __shared__ float qs[16][64];
    __shared__ float ks[64][65];
    __shared__ float vs[64][65];
    __shared__ float ls[16][64];

    #pragma unroll
    for (int i = 0; i < 8; i++) {
        int idx = i * 128 + t;
        int a = idx >> 6, d = idx & 63;
        qs[a][d] = q[(size_t)(bt * 16 + a) * 512 + h * 64 + d];
    }
    #pragma unroll
    for (int i = 0; i < 32; i++) {
        int idx = i * 128 + t;
        int e = idx >> 6, d = idx & 63;
        const float* base = kv + (size_t)(bt * 64 + e) * 1024 + h * 64 + d;
        ks[e][d] = base[0];
        vs[e][d] = base[512];
    }
    __syncthreads();

    #pragma unroll
    for (int i = 0; i < 8; i++) {
        int idx = i * 128 + t;
        int a = idx >> 6, e = idx & 63;
        float s = 0.f;
        #pragma unroll
        for (int d = 0; d < 64; d++) s += qs[a][d] * ks[e][d];
        s *= 0.125f;
        if (obs[(size_t)bt * 4096 + a * 64 + e] != 0u) s = -1e30f;
        ls[a][e] = s;
    }
    __syncthreads();

    const int warp = t >> 5, lane = t & 31;
    #pragma unroll
    for (int r = 0; r < 4; r++) {
        int a = warp * 4 + r;
        float x0 = ls[a][lane], x1 = ls[a][lane + 32];
        float mx = fmaxf(x0, x1);
        #pragma unroll
        for (int o = 16; o; o >>= 1) mx = fmaxf(mx, __shfl_xor_sync(0xffffffffu, mx, o));
        float e0 = __expf(x0 - mx), e1 = __expf(x1 - mx);
        float sm = e0 + e1;
        #pragma unroll
        for (int o = 16; o; o >>= 1) sm += __shfl_xor_sync(0xffffffffu, sm, o);
        float inv = (mx <= -1e29f) ? 0.f : (1.f / sm);
        ls[a][lane] = e0 * inv;
        ls[a][lane + 32] = e1 * inv;
    }
    __syncthreads();

    #pragma unroll
    for (int i = 0; i < 8; i++) {
        int idx = i * 128 + t;
        int a = idx >> 6, d = idx & 63;
        float s = 0.f;
        #pragma unroll
        for (int e = 0; e < 64; e++) s += ls[a][e] * vs[e][d];
        attn[(size_t)(bt * 16 + a) * 512 + h * 64 + d] = s;
    }
}

// ---------------------------------------------------------------------------
extern "C" void kernel_launch(void* const* d_in, const int* in_sizes, int n_in,
                              void* d_out, int out_size)
{
    (void)in_sizes; (void)n_in; (void)out_size;
    const float*    entities    = (const float*)d_in[0];
    const unsigned* obs_mask    = (const unsigned*)d_in[1];
    const unsigned* entity_mask = (const unsigned*)d_in[2];
    const float*    W1    = (const float*)d_in[3];
    const float*    b1    = (const float*)d_in[4];
    const float*    Win   = (const float*)d_in[5];
    const float*    Wout  = (const float*)d_in[6];
    const float*    b_out = (const float*)d_in[7];
    const float*    W2    = (const float*)d_in[8];
    const float*    b2    = (const float*)d_in[9];
    float* out = (float*)d_out;

    float *x1, *kvp, *qp, *attnp, *hp;
    cudaGetSymbolAddress((void**)&x1,    g_x1);
    cudaGetSymbolAddress((void**)&kvp,   g_kv);
    cudaGetSymbolAddress((void**)&qp,    g_q);
    cudaGetSymbolAddress((void**)&attnp, g_attn);
    cudaGetSymbolAddress((void**)&hp,    g_h);

    // 1) x1 = relu(entities @ W1^T + b1)        [131072, 512], K=128
    gemm_f16x3<<<dim3(512 / 128, M_X1 / 128), 256>>>(
        entities, W1, x1, M_X1, 512, 128, b1, nullptr, 1);

    // 2) kv = x1 @ Win[512:1536]^T              [131072, 1024], K=512
    gemm_f16x3<<<dim3(1024 / 128, M_X1 / 128), 256>>>(
        x1, Win + (size_t)512 * 512, kvp, M_X1, 1024, 512, nullptr, nullptr, 0);

    // 3) q = x1[agent rows] @ Win[0:512]^T      [32768, 512], K=512
    gemm_f16x3<<<dim3(512 / 128, M_AG / 128), 256>>>(
        x1, Win, qp, M_AG, 512, 512, nullptr, nullptr, 4);

    // 4) masked multi-head attention
    attn_kernel<<<dim3(8, BT_), 128>>>(qp, kvp, obs_mask, attnp);

    // 5) h = agent_mask ? 0 : relu(attn @ Wout^T + b_out)
    gemm_f16x3<<<dim3(512 / 128, M_AG / 128), 256>>>(
        attnp, Wout, hp, M_AG, 512, 512, b_out, entity_mask, 3);

    // 6) out = relu(h @ W2^T + b2)
    gemm_f16x3<<<dim3(512 / 128, M_AG / 128), 256>>>(
        hp, W2, out, M_AG, 512, 512, b2, nullptr, 1);
}

// round 5
// speedup vs baseline: 2.1595x; 1.1234x over previous
#include <cuda_runtime.h>
#include <cuda_fp16.h>
#include <cstdint>
#include <cstddef>

// B=32,T=64 -> BT=2048; NE=64; NA=16; ED=128; E=512; H=8; HD=64; R=512
#define BT_   2048
#define M_X1  131072
#define M_AG  32768

// ---------------------------------------------------------------------------
// fp16 hi/lo split operand storage (device globals; allocation forbidden)
// ---------------------------------------------------------------------------
__device__ __half g_enth[(size_t)M_X1 * 128], g_entl[(size_t)M_X1 * 128];
__device__ __half g_x1h [(size_t)M_X1 * 512], g_x1l [(size_t)M_X1 * 512];
__device__ __half g_kvh [(size_t)M_X1 * 1024], g_kvl[(size_t)M_X1 * 1024];
__device__ __half g_ath [(size_t)M_AG * 512], g_atl [(size_t)M_AG * 512];
__device__ __half g_hh  [(size_t)M_AG * 512], g_hl  [(size_t)M_AG * 512];
__device__ __half g_qh  [(size_t)M_AG * 512], g_ql  [(size_t)M_AG * 512];
__device__ __half g_W1h [512 * 128],  g_W1l [512 * 128];
__device__ __half g_Winh[1536 * 512], g_Winl[1536 * 512];
__device__ __half g_Woh [512 * 512],  g_Wol [512 * 512];
__device__ __half g_W2h [512 * 512],  g_W2l [512 * 512];

// ---------------------------------------------------------------------------
__device__ __forceinline__ uint32_t smem_u32(const void* p) {
    uint32_t a;
    asm("{ .reg .u64 t; cvta.to.shared.u64 t, %1; cvt.u32.u64 %0, t; }" : "=r"(a) : "l"(p));
    return a;
}

#define LDSM4(r, a) \
    asm volatile("ldmatrix.sync.aligned.m8n8.x4.shared.b16 {%0,%1,%2,%3}, [%4];" \
        : "=r"((r)[0]), "=r"((r)[1]), "=r"((r)[2]), "=r"((r)[3]) : "r"(a))

#define CP16(d, s)  asm volatile("cp.async.cg.shared.global [%0], [%1], 16;" :: "r"(d), "l"(s))
#define CPCOMMIT()  asm volatile("cp.async.commit_group;" ::: "memory")
#define CPWAIT1()   asm volatile("cp.async.wait_group 1;" ::: "memory")

__device__ __forceinline__ void mma16(float* d, const uint32_t* a, const uint32_t* b) {
    asm volatile(
        "mma.sync.aligned.m16n8k16.row.col.f32.f16.f16.f32 "
        "{%0,%1,%2,%3},{%4,%5,%6,%7},{%8,%9},{%0,%1,%2,%3};\n"
        : "+f"(d[0]), "+f"(d[1]), "+f"(d[2]), "+f"(d[3])
        : "r"(a[0]), "r"(a[1]), "r"(a[2]), "r"(a[3]), "r"(b[0]), "r"(b[1]));
}

// ---------------------------------------------------------------------------
// split kernel: fp32 -> fp16 hi + fp16 lo residual (elementwise, vec4)
// ---------------------------------------------------------------------------
__global__ void split_kernel(const float4* __restrict__ x,
                             uint2* __restrict__ hi, uint2* __restrict__ lo, int n4)
{
    int i = blockIdx.x * blockDim.x + threadIdx.x;
    if (i >= n4) return;
    float4 v = x[i];
    half2 h0 = __floats2half2_rn(v.x, v.y);
    half2 h1 = __floats2half2_rn(v.z, v.w);
    float2 f0 = __half22float2(h0), f1 = __half22float2(h1);
    half2 l0 = __floats2half2_rn(v.x - f0.x, v.y - f0.y);
    half2 l1 = __floats2half2_rn(v.z - f1.x, v.w - f1.y);
    hi[i] = make_uint2(*(uint32_t*)&h0, *(uint32_t*)&h1);
    lo[i] = make_uint2(*(uint32_t*)&l0, *(uint32_t*)&l1);
}

// ---------------------------------------------------------------------------
// fp16x3 NT GEMM, ldmatrix + cp.async double-buffer.
// C = epi(A*B^T + bias); A,B given as hi/lo fp16 pairs.
//   flags bit0: relu   bit1: zero masked rows   bit2: gather A rows
//   flags bit3: write fp32 to Cf (else split to Ch/Cl)
// Block 128x128, K-chunk 32, 256 threads (8 warps 4Mx2N), warp 32x64.
// smem rows: 80B stride -> conflict-free ldmatrix (5i mod 8 permutation).
// ---------------------------------------------------------------------------
#define ROWB 80
#define OAH  0
#define OAL  10240
#define OBH  20480
#define OBL  30720
#define BUFB 40960
#define GSMEM (2 * BUFB)

__global__ __launch_bounds__(256, 2) void gemm_v2(
    const __half* __restrict__ Ah, const __half* __restrict__ Al,
    const __half* __restrict__ Bh, const __half* __restrict__ Bl,
    __half* __restrict__ Ch, __half* __restrict__ Cl, float* __restrict__ Cf,
    int M, int N, int K,
    const float* __restrict__ bias, const unsigned* __restrict__ emask, int flags)
{
    extern __shared__ char sm_[];
    const uint32_t sb = smem_u32(sm_);
    const int tid = threadIdx.x, lane = tid & 31, warp = tid >> 5;
    const int wm = warp >> 1, wn = warp & 1;
    const int bm = blockIdx.y * 128, bn = blockIdx.x * 128;
    const int CCH = K >> 5;

    // staging: thread covers rows srow, srow+64; 16B seg sseg
    const int srow = tid >> 2, sseg = tid & 3;
    size_t aoff[2], boff[2];
    #pragma unroll
    for (int p = 0; p < 2; p++) {
        int grow = bm + srow + 64 * p;
        int arow = (flags & 4) ? ((grow >> 4) * 64 + (grow & 15)) : grow;
        aoff[p] = (size_t)arow * K + sseg * 8;
        boff[p] = (size_t)(bn + srow + 64 * p) * K + sseg * 8;
    }
    const uint32_t sdst = (uint32_t)(srow * ROWB + sseg * 16);

    #define STAGE(c) do {                                               \
        uint32_t base_ = sb + ((c) & 1) * BUFB;                          \
        int k0_ = (c) << 5;                                              \
        _Pragma("unroll")                                                \
        for (int p_ = 0; p_ < 2; p_++) {                                 \
            uint32_t d_ = base_ + sdst + p_ * 64 * ROWB;                 \
            CP16(d_ + OAH, Ah + aoff[p_] + k0_);                         \
            CP16(d_ + OAL, Al + aoff[p_] + k0_);                         \
            CP16(d_ + OBH, Bh + boff[p_] + k0_);                         \
            CP16(d_ + OBL, Bl + boff[p_] + k0_);                         \
        }                                                                \
    } while (0)

    float acc[2][8][4];
    #pragma unroll
    for (int i = 0; i < 2; i++)
        #pragma unroll
        for (int j = 0; j < 8; j++)
            #pragma unroll
            for (int t = 0; t < 4; t++) acc[i][j][t] = 0.f;

    // ldmatrix per-lane offsets
    const uint32_t aOff = (uint32_t)((wm * 32 + (lane & 15)) * ROWB + (lane >> 4) * 16);
    const uint32_t bOff = (uint32_t)((wn * 64 + lane) * ROWB);

    STAGE(0); CPCOMMIT();
    STAGE(1); CPCOMMIT();

    for (int c = 0; c < CCH; c++) {
        CPWAIT1();
        __syncthreads();
        const uint32_t base = sb + (c & 1) * BUFB;

        #pragma unroll
        for (int step = 0; step < 2; step++) {
            uint32_t ah[2][4], alr[2][4], b[8][2], r[4];
            // A hi (x4 covers k..k+15 for 16 rows)
            #pragma unroll
            for (int mf = 0; mf < 2; mf++)
                LDSM4(ah[mf], base + OAH + aOff + mf * 16 * ROWB + step * 32);
            // B hi
            #pragma unroll
            for (int q = 0; q < 2; q++)
                #pragma unroll
                for (int kh = 0; kh < 2; kh++) {
                    LDSM4(r, base + OBH + bOff + q * 32 * ROWB + step * 32 + kh * 16);
                    b[q * 4 + 0][kh] = r[0]; b[q * 4 + 1][kh] = r[1];
                    b[q * 4 + 2][kh] = r[2]; b[q * 4 + 3][kh] = r[3];
                }
            // term 1: hi*hi (16 independent accs)
            #pragma unroll
            for (int nf = 0; nf < 8; nf++)
                #pragma unroll
                for (int mf = 0; mf < 2; mf++)
                    mma16(acc[mf][nf], ah[mf], b[nf]);
            // A lo, term 2: lo*hi
            #pragma unroll
            for (int mf = 0; mf < 2; mf++)
                LDSM4(alr[mf], base + OAL + aOff + mf * 16 * ROWB + step * 32);
            #pragma unroll
            for (int nf = 0; nf < 8; nf++)
                #pragma unroll
                for (int mf = 0; mf < 2; mf++)
                    mma16(acc[mf][nf], alr[mf], b[nf]);
            // B lo, term 3: hi*lo
            #pragma unroll
            for (int q = 0; q < 2; q++)
                #pragma unroll
                for (int kh = 0; kh < 2; kh++) {
                    LDSM4(r, base + OBL + bOff + q * 32 * ROWB + step * 32 + kh * 16);
                    b[q * 4 + 0][kh] = r[0]; b[q * 4 + 1][kh] = r[1];
                    b[q * 4 + 2][kh] = r[2]; b[q * 4 + 3][kh] = r[3];
                }
            #pragma unroll
            for (int nf = 0; nf < 8; nf++)
                #pragma unroll
                for (int mf = 0; mf < 2; mf++)
                    mma16(acc[mf][nf], ah[mf], b[nf]);
        }
        __syncthreads();
        if (c + 2 < CCH) STAGE(c + 2);
        CPCOMMIT();
    }
    #undef STAGE

    // epilogue
    const int gid = lane >> 2, tig = lane & 3;
    #pragma unroll
    for (int mf = 0; mf < 2; mf++) {
        int r0 = bm + wm * 32 + mf * 16 + gid;      // rows r0, r0+8
        bool z0 = false, z1 = false;
        if (flags & 2) {
            int e0 = ((r0    ) >> 4) * 64 + ((r0    ) & 15);
            int e1 = ((r0 + 8) >> 4) * 64 + ((r0 + 8) & 15);
            z0 = (emask[e0] != 0u);
            z1 = (emask[e1] != 0u);
        }
        #pragma unroll
        for (int nf = 0; nf < 8; nf++) {
            int c = bn + wn * 64 + nf * 8 + tig * 2;
            float b0 = bias ? bias[c] : 0.f;
            float b1 = bias ? bias[c + 1] : 0.f;
            float v0 = acc[mf][nf][0] + b0;
            float v1 = acc[mf][nf][1] + b1;
            float v2 = acc[mf][nf][2] + b0;
            float v3 = acc[mf][nf][3] + b1;
            if (flags & 1) {
                v0 = fmaxf(v0, 0.f); v1 = fmaxf(v1, 0.f);
                v2 = fmaxf(v2, 0.f); v3 = fmaxf(v3, 0.f);
            }
            if (z0) { v0 = 0.f; v1 = 0.f; }
            if (z1) { v2 = 0.f; v3 = 0.f; }
            if (flags & 8) {
                *(float2*)(Cf + (size_t)r0 * N + c)       = make_float2(v0, v1);
                *(float2*)(Cf + (size_t)(r0 + 8) * N + c) = make_float2(v2, v3);
            } else {
                half2 h01 = __floats2half2_rn(v0, v1);
                half2 h23 = __floats2half2_rn(v2, v3);
                float2 f01 = __half22float2(h01), f23 = __half22float2(h23);
                half2 l01 = __floats2half2_rn(v0 - f01.x, v1 - f01.y);
                half2 l23 = __floats2half2_rn(v2 - f23.x, v3 - f23.y);
                *(uint32_t*)(Ch + (size_t)r0 * N + c)       = *(uint32_t*)&h01;
                *(uint32_t*)(Cl + (size_t)r0 * N + c)       = *(uint32_t*)&l01;
                *(uint32_t*)(Ch + (size_t)(r0 + 8) * N + c) = *(uint32_t*)&h23;
                *(uint32_t*)(Cl + (size_t)(r0 + 8) * N + c) = *(uint32_t*)&l23;
            }
        }
    }
}

// ---------------------------------------------------------------------------
// Attention: one block per (head, bt). 128 threads. hi/lo in, hi/lo out.
// ---------------------------------------------------------------------------
__global__ __launch_bounds__(128) void attn_kernel(
    const __half* __restrict__ qh, const __half* __restrict__ ql,
    const __half* __restrict__ kvh, const __half* __restrict__ kvl,
    const unsigned* __restrict__ obs,
    __half* __restrict__ ath, __half* __restrict__ atl)
{
    const int h = blockIdx.x;
    const int bt = blockIdx.y;
    const int t = threadIdx.x;

    __shared__ float qs[16][64];
    __shared__ float ks[64][65];
    __shared__ float vs[64][65];
    __shared__ float ls[16][64];

    #pragma unroll
    for (int i = 0; i < 8; i++) {
        int idx = i * 128 + t;
        int a = idx >> 6, d = idx & 63;
        size_t g = (size_t)(bt * 16 + a) * 512 + h * 64 + d;
        qs[a][d] = __half2float(qh[g]) + __half2float(ql[g]);
    }
    #pragma unroll
    for (int i = 0; i < 32; i++) {
        int idx = i * 128 + t;
        int e = idx >> 6, d = idx & 63;
        size_t g = (size_t)(bt * 64 + e) * 1024 + h * 64 + d;
        ks[e][d] = __half2float(kvh[g])       + __half2float(kvl[g]);
        vs[e][d] = __half2float(kvh[g + 512]) + __half2float(kvl[g + 512]);
    }
    __syncthreads();

    #pragma unroll
    for (int i = 0; i < 8; i++) {
        int idx = i * 128 + t;
        int a = idx >> 6, e = idx & 63;
        float s = 0.f;
        #pragma unroll
        for (int d = 0; d < 64; d++) s += qs[a][d] * ks[e][d];
        s *= 0.125f;
        if (obs[(size_t)bt * 4096 + a * 64 + e] != 0u) s = -1e30f;
        ls[a][e] = s;
    }
    __syncthreads();

    const int warp = t >> 5, lane = t & 31;
    #pragma unroll
    for (int r = 0; r < 4; r++) {
        int a = warp * 4 + r;
        float x0 = ls[a][lane], x1 = ls[a][lane + 32];
        float mx = fmaxf(x0, x1);
        #pragma unroll
        for (int o = 16; o; o >>= 1) mx = fmaxf(mx, __shfl_xor_sync(0xffffffffu, mx, o));
        float e0 = __expf(x0 - mx), e1 = __expf(x1 - mx);
        float smv = e0 + e1;
        #pragma unroll
        for (int o = 16; o; o >>= 1) smv += __shfl_xor_sync(0xffffffffu, smv, o);
        float inv = (mx <= -1e29f) ? 0.f : (1.f / smv);
        ls[a][lane] = e0 * inv;
        ls[a][lane + 32] = e1 * inv;
    }
    __syncthreads();

    #pragma unroll
    for (int i = 0; i < 8; i++) {
        int idx = i * 128 + t;
        int a = idx >> 6, d = idx & 63;
        float s = 0.f;
        #pragma unroll
        for (int e = 0; e < 64; e++) s += ls[a][e] * vs[e][d];
        size_t g = (size_t)(bt * 16 + a) * 512 + h * 64 + d;
        __half hs = __float2half_rn(s);
        __half lsv = __float2half_rn(s - __half2float(hs));
        ath[g] = hs;
        atl[g] = lsv;
    }
}

// ---------------------------------------------------------------------------
extern "C" void kernel_launch(void* const* d_in, const int* in_sizes, int n_in,
                              void* d_out, int out_size)
{
    (void)in_sizes; (void)n_in; (void)out_size;
    const float*    entities    = (const float*)d_in[0];
    const unsigned* obs_mask    = (const unsigned*)d_in[1];
    const unsigned* entity_mask = (const unsigned*)d_in[2];
    const float*    W1    = (const float*)d_in[3];
    const float*    b1    = (const float*)d_in[4];
    const float*    Win   = (const float*)d_in[5];
    const float*    Wout  = (const float*)d_in[6];
    const float*    b_out = (const float*)d_in[7];
    const float*    W2    = (const float*)d_in[8];
    const float*    b2    = (const float*)d_in[9];
    float* out = (float*)d_out;

    __half *enth, *entl, *x1h, *x1l, *kvh, *kvl, *qh, *ql, *ath, *atl, *hh, *hl;
    __half *w1h, *w1l, *winh, *winl, *woh, *wol, *w2h, *w2l;
    cudaGetSymbolAddress((void**)&enth, g_enth); cudaGetSymbolAddress((void**)&entl, g_entl);
    cudaGetSymbolAddress((void**)&x1h,  g_x1h);  cudaGetSymbolAddress((void**)&x1l,  g_x1l);
    cudaGetSymbolAddress((void**)&kvh,  g_kvh);  cudaGetSymbolAddress((void**)&kvl,  g_kvl);
    cudaGetSymbolAddress((void**)&qh,   g_qh);   cudaGetSymbolAddress((void**)&ql,   g_ql);
    cudaGetSymbolAddress((void**)&ath,  g_ath);  cudaGetSymbolAddress((void**)&atl,  g_atl);
    cudaGetSymbolAddress((void**)&hh,   g_hh);   cudaGetSymbolAddress((void**)&hl,   g_hl);
    cudaGetSymbolAddress((void**)&w1h,  g_W1h);  cudaGetSymbolAddress((void**)&w1l,  g_W1l);
    cudaGetSymbolAddress((void**)&winh, g_Winh); cudaGetSymbolAddress((void**)&winl, g_Winl);
    cudaGetSymbolAddress((void**)&woh,  g_Woh);  cudaGetSymbolAddress((void**)&wol,  g_Wol);
    cudaGetSymbolAddress((void**)&w2h,  g_W2h);  cudaGetSymbolAddress((void**)&w2l,  g_W2l);

    cudaFuncSetAttribute(gemm_v2, cudaFuncAttributeMaxDynamicSharedMemorySize, GSMEM);

    // 0) split inputs / weights to fp16 hi/lo
    auto split = [&](const float* src, __half* hi, __half* lo, size_t n) {
        int n4 = (int)(n / 4);
        split_kernel<<<(n4 + 255) / 256, 256>>>(
            (const float4*)src, (uint2*)hi, (uint2*)lo, n4);
    };
    split(entities, enth, entl, (size_t)M_X1 * 128);
    split(W1,   w1h,  w1l,  (size_t)512 * 128);
    split(Win,  winh, winl, (size_t)1536 * 512);
    split(Wout, woh,  wol,  (size_t)512 * 512);
    split(W2,   w2h,  w2l,  (size_t)512 * 512);

    // 1) x1 = relu(entities @ W1^T + b1)   [131072,512], K=128
    gemm_v2<<<dim3(4, 1024), 256, GSMEM>>>(
        enth, entl, w1h, w1l, x1h, x1l, nullptr,
        M_X1, 512, 128, b1, nullptr, 1);

    // 2) kv = x1 @ Win[512:1536]^T         [131072,1024], K=512
    gemm_v2<<<dim3(8, 1024), 256, GSMEM>>>(
        x1h, x1l, winh + (size_t)512 * 512, winl + (size_t)512 * 512, kvh, kvl, nullptr,
        M_X1, 1024, 512, nullptr, nullptr, 0);

    // 3) q = x1[agents] @ Win[0:512]^T     [32768,512], K=512
    gemm_v2<<<dim3(4, 256), 256, GSMEM>>>(
        x1h, x1l, winh, winl, qh, ql, nullptr,
        M_AG, 512, 512, nullptr, nullptr, 4);

    // 4) masked multi-head attention
    attn_kernel<<<dim3(8, BT_), 128>>>(qh, ql, kvh, kvl, obs_mask, ath, atl);

    // 5) h = mask0(relu(attn @ Wout^T + b_out))
    gemm_v2<<<dim3(4, 256), 256, GSMEM>>>(
        ath, atl, woh, wol, hh, hl, nullptr,
        M_AG, 512, 512, b_out, entity_mask, 3);

    // 6) out = relu(h @ W2^T + b2) -> fp32
    gemm_v2<<<dim3(4, 256), 256, GSMEM>>>(
        hh, hl, w2h, w2l, nullptr, nullptr, out,
        M_AG, 512, 512, b2, nullptr, 1 | 8);
}

// round 6
// speedup vs baseline: 2.2886x; 1.0598x over previous
#include <cuda_runtime.h>
#include <cuda_fp16.h>
#include <cstdint>
#include <cstddef>

// B=32,T=64 -> BT=2048; NE=64; NA=16; ED=128; E=512; H=8; HD=64; R=512
#define BT_   2048
#define M_X1  131072
#define M_AG  32768

// ---------------------------------------------------------------------------
// fp16 hi/lo split operand storage (device globals; allocation forbidden)
// ---------------------------------------------------------------------------
__device__ __half g_enth[(size_t)M_X1 * 128], g_entl[(size_t)M_X1 * 128];
__device__ __half g_x1h [(size_t)M_X1 * 512], g_x1l [(size_t)M_X1 * 512];
__device__ __half g_kvh [(size_t)M_X1 * 1024], g_kvl[(size_t)M_X1 * 1024];
__device__ __half g_ath [(size_t)M_AG * 512], g_atl [(size_t)M_AG * 512];
__device__ __half g_hh  [(size_t)M_AG * 512], g_hl  [(size_t)M_AG * 512];
__device__ __half g_qh  [(size_t)M_AG * 512], g_ql  [(size_t)M_AG * 512];
__device__ __half g_W1h [512 * 128],  g_W1l [512 * 128];
__device__ __half g_Winh[1536 * 512], g_Winl[1536 * 512];
__device__ __half g_Woh [512 * 512],  g_Wol [512 * 512];
__device__ __half g_W2h [512 * 512],  g_W2l [512 * 512];

// ---------------------------------------------------------------------------
__device__ __forceinline__ uint32_t smem_u32(const void* p) {
    uint32_t a;
    asm("{ .reg .u64 t; cvta.to.shared.u64 t, %1; cvt.u32.u64 %0, t; }" : "=r"(a) : "l"(p));
    return a;
}

#define LDSM4(r, a) \
    asm volatile("ldmatrix.sync.aligned.m8n8.x4.shared.b16 {%0,%1,%2,%3}, [%4];" \
        : "=r"((r)[0]), "=r"((r)[1]), "=r"((r)[2]), "=r"((r)[3]) : "r"(a))

#define CP16(d, s)  asm volatile("cp.async.cg.shared.global [%0], [%1], 16;" :: "r"(d), "l"(s))
#define CPCOMMIT()  asm volatile("cp.async.commit_group;" ::: "memory")
#define CPWAIT1()   asm volatile("cp.async.wait_group 1;" ::: "memory")

__device__ __forceinline__ void mma16(float* d, const uint32_t* a, const uint32_t* b) {
    asm volatile(
        "mma.sync.aligned.m16n8k16.row.col.f32.f16.f16.f32 "
        "{%0,%1,%2,%3},{%4,%5,%6,%7},{%8,%9},{%0,%1,%2,%3};\n"
        : "+f"(d[0]), "+f"(d[1]), "+f"(d[2]), "+f"(d[3])
        : "r"(a[0]), "r"(a[1]), "r"(a[2]), "r"(a[3]), "r"(b[0]), "r"(b[1]));
}

// ---------------------------------------------------------------------------
// split kernel: fp32 -> fp16 hi + fp16 lo residual (elementwise, vec4)
// ---------------------------------------------------------------------------
__global__ void split_kernel(const float4* __restrict__ x,
                             uint2* __restrict__ hi, uint2* __restrict__ lo, int n4)
{
    int i = blockIdx.x * blockDim.x + threadIdx.x;
    if (i >= n4) return;
    float4 v = x[i];
    half2 h0 = __floats2half2_rn(v.x, v.y);
    half2 h1 = __floats2half2_rn(v.z, v.w);
    float2 f0 = __half22float2(h0), f1 = __half22float2(h1);
    half2 l0 = __floats2half2_rn(v.x - f0.x, v.y - f0.y);
    half2 l1 = __floats2half2_rn(v.z - f1.x, v.w - f1.y);
    hi[i] = make_uint2(*(uint32_t*)&h0, *(uint32_t*)&h1);
    lo[i] = make_uint2(*(uint32_t*)&l0, *(uint32_t*)&l1);
}

// ---------------------------------------------------------------------------
// fp16x3 NT GEMM (unchanged from R5 — at legacy-HMMA rate ceiling)
// ---------------------------------------------------------------------------
#define ROWB 80
#define OAH  0
#define OAL  10240
#define OBH  20480
#define OBL  30720
#define BUFB 40960
#define GSMEM (2 * BUFB)

__global__ __launch_bounds__(256, 2) void gemm_v2(
    const __half* __restrict__ Ah, const __half* __restrict__ Al,
    const __half* __restrict__ Bh, const __half* __restrict__ Bl,
    __half* __restrict__ Ch, __half* __restrict__ Cl, float* __restrict__ Cf,
    int M, int N, int K,
    const float* __restrict__ bias, const unsigned* __restrict__ emask, int flags)
{
    extern __shared__ char sm_[];
    const uint32_t sb = smem_u32(sm_);
    const int tid = threadIdx.x, lane = tid & 31, warp = tid >> 5;
    const int wm = warp >> 1, wn = warp & 1;
    const int bm = blockIdx.y * 128, bn = blockIdx.x * 128;
    const int CCH = K >> 5;

    const int srow = tid >> 2, sseg = tid & 3;
    size_t aoff[2], boff[2];
    #pragma unroll
    for (int p = 0; p < 2; p++) {
        int grow = bm + srow + 64 * p;
        int arow = (flags & 4) ? ((grow >> 4) * 64 + (grow & 15)) : grow;
        aoff[p] = (size_t)arow * K + sseg * 8;
        boff[p] = (size_t)(bn + srow + 64 * p) * K + sseg * 8;
    }
    const uint32_t sdst = (uint32_t)(srow * ROWB + sseg * 16);

    #define STAGE(c) do {                                               \
        uint32_t base_ = sb + ((c) & 1) * BUFB;                          \
        int k0_ = (c) << 5;                                              \
        _Pragma("unroll")                                                \
        for (int p_ = 0; p_ < 2; p_++) {                                 \
            uint32_t d_ = base_ + sdst + p_ * 64 * ROWB;                 \
            CP16(d_ + OAH, Ah + aoff[p_] + k0_);                         \
            CP16(d_ + OAL, Al + aoff[p_] + k0_);                         \
            CP16(d_ + OBH, Bh + boff[p_] + k0_);                         \
            CP16(d_ + OBL, Bl + boff[p_] + k0_);                         \
        }                                                                \
    } while (0)

    float acc[2][8][4];
    #pragma unroll
    for (int i = 0; i < 2; i++)
        #pragma unroll
        for (int j = 0; j < 8; j++)
            #pragma unroll
            for (int t = 0; t < 4; t++) acc[i][j][t] = 0.f;

    const uint32_t aOff = (uint32_t)((wm * 32 + (lane & 15)) * ROWB + (lane >> 4) * 16);
    const uint32_t bOff = (uint32_t)((wn * 64 + lane) * ROWB);

    STAGE(0); CPCOMMIT();
    STAGE(1); CPCOMMIT();

    for (int c = 0; c < CCH; c++) {
        CPWAIT1();
        __syncthreads();
        const uint32_t base = sb + (c & 1) * BUFB;

        #pragma unroll
        for (int step = 0; step < 2; step++) {
            uint32_t ah[2][4], alr[2][4], b[8][2], r[4];
            #pragma unroll
            for (int mf = 0; mf < 2; mf++)
                LDSM4(ah[mf], base + OAH + aOff + mf * 16 * ROWB + step * 32);
            #pragma unroll
            for (int q = 0; q < 2; q++)
                #pragma unroll
                for (int kh = 0; kh < 2; kh++) {
                    LDSM4(r, base + OBH + bOff + q * 32 * ROWB + step * 32 + kh * 16);
                    b[q * 4 + 0][kh] = r[0]; b[q * 4 + 1][kh] = r[1];
                    b[q * 4 + 2][kh] = r[2]; b[q * 4 + 3][kh] = r[3];
                }
            #pragma unroll
            for (int nf = 0; nf < 8; nf++)
                #pragma unroll
                for (int mf = 0; mf < 2; mf++)
                    mma16(acc[mf][nf], ah[mf], b[nf]);
            #pragma unroll
            for (int mf = 0; mf < 2; mf++)
                LDSM4(alr[mf], base + OAL + aOff + mf * 16 * ROWB + step * 32);
            #pragma unroll
            for (int nf = 0; nf < 8; nf++)
                #pragma unroll
                for (int mf = 0; mf < 2; mf++)
                    mma16(acc[mf][nf], alr[mf], b[nf]);
            #pragma unroll
            for (int q = 0; q < 2; q++)
                #pragma unroll
                for (int kh = 0; kh < 2; kh++) {
                    LDSM4(r, base + OBL + bOff + q * 32 * ROWB + step * 32 + kh * 16);
                    b[q * 4 + 0][kh] = r[0]; b[q * 4 + 1][kh] = r[1];
                    b[q * 4 + 2][kh] = r[2]; b[q * 4 + 3][kh] = r[3];
                }
            #pragma unroll
            for (int nf = 0; nf < 8; nf++)
                #pragma unroll
                for (int mf = 0; mf < 2; mf++)
                    mma16(acc[mf][nf], ah[mf], b[nf]);
        }
        __syncthreads();
        if (c + 2 < CCH) STAGE(c + 2);
        CPCOMMIT();
    }
    #undef STAGE

    const int gid = lane >> 2, tig = lane & 3;
    #pragma unroll
    for (int mf = 0; mf < 2; mf++) {
        int r0 = bm + wm * 32 + mf * 16 + gid;
        bool z0 = false, z1 = false;
        if (flags & 2) {
            int e0 = ((r0    ) >> 4) * 64 + ((r0    ) & 15);
            int e1 = ((r0 + 8) >> 4) * 64 + ((r0 + 8) & 15);
            z0 = (emask[e0] != 0u);
            z1 = (emask[e1] != 0u);
        }
        #pragma unroll
        for (int nf = 0; nf < 8; nf++) {
            int c = bn + wn * 64 + nf * 8 + tig * 2;
            float b0 = bias ? bias[c] : 0.f;
            float b1 = bias ? bias[c + 1] : 0.f;
            float v0 = acc[mf][nf][0] + b0;
            float v1 = acc[mf][nf][1] + b1;
            float v2 = acc[mf][nf][2] + b0;
            float v3 = acc[mf][nf][3] + b1;
            if (flags & 1) {
                v0 = fmaxf(v0, 0.f); v1 = fmaxf(v1, 0.f);
                v2 = fmaxf(v2, 0.f); v3 = fmaxf(v3, 0.f);
            }
            if (z0) { v0 = 0.f; v1 = 0.f; }
            if (z1) { v2 = 0.f; v3 = 0.f; }
            if (flags & 8) {
                *(float2*)(Cf + (size_t)r0 * N + c)       = make_float2(v0, v1);
                *(float2*)(Cf + (size_t)(r0 + 8) * N + c) = make_float2(v2, v3);
            } else {
                half2 h01 = __floats2half2_rn(v0, v1);
                half2 h23 = __floats2half2_rn(v2, v3);
                float2 f01 = __half22float2(h01), f23 = __half22float2(h23);
                half2 l01 = __floats2half2_rn(v0 - f01.x, v1 - f01.y);
                half2 l23 = __floats2half2_rn(v2 - f23.x, v3 - f23.y);
                *(uint32_t*)(Ch + (size_t)r0 * N + c)       = *(uint32_t*)&h01;
                *(uint32_t*)(Cl + (size_t)r0 * N + c)       = *(uint32_t*)&l01;
                *(uint32_t*)(Ch + (size_t)(r0 + 8) * N + c) = *(uint32_t*)&h23;
                *(uint32_t*)(Cl + (size_t)(r0 + 8) * N + c) = *(uint32_t*)&l23;
            }
        }
    }
}

// ---------------------------------------------------------------------------
// MMA attention: block per bt (256 thr), warp = head.
// S = (Q·K^T)/8 masked, softmax in-fragment, O = W·V. fp16x3/x2.5 split math.
// Fragments loaded straight from gmem (q/k contiguous u32 pairs; V scalar).
// ---------------------------------------------------------------------------
__global__ __launch_bounds__(256) void attn_mma(
    const __half* __restrict__ qh, const __half* __restrict__ ql,
    const __half* __restrict__ kvh, const __half* __restrict__ kvl,
    const unsigned* __restrict__ obs,
    __half* __restrict__ ath, __half* __restrict__ atl)
{
    const int bt = blockIdx.x;
    const int h = threadIdx.x >> 5;
    const int lane = threadIdx.x & 31;
    const int gid = lane >> 2, tig = lane & 3;

    __shared__ unsigned ms[1024];     // obs[bt] : 16 x 64
    #pragma unroll
    for (int i = 0; i < 4; i++) ms[threadIdx.x + 256 * i] = obs[(size_t)bt * 4096 + threadIdx.x + 256 * i];
    __syncthreads();

    const size_t qb  = (size_t)(bt * 16) * 512 + h * 64;
    const size_t kvb = (size_t)(bt * 64) * 1024 + h * 64;

    // ---- S = Q K^T ----
    float s[8][4];
    #pragma unroll
    for (int nf = 0; nf < 8; nf++)
        #pragma unroll
        for (int j = 0; j < 4; j++) s[nf][j] = 0.f;

    #pragma unroll
    for (int t = 0; t < 4; t++) {
        const int d = t * 16 + 2 * tig;
        uint32_t a_h[4], a_l[4];
        a_h[0] = *(const uint32_t*)(qh + qb + (size_t)gid * 512 + d);
        a_h[1] = *(const uint32_t*)(qh + qb + (size_t)(gid + 8) * 512 + d);
        a_h[2] = *(const uint32_t*)(qh + qb + (size_t)gid * 512 + d + 8);
        a_h[3] = *(const uint32_t*)(qh + qb + (size_t)(gid + 8) * 512 + d + 8);
        a_l[0] = *(const uint32_t*)(ql + qb + (size_t)gid * 512 + d);
        a_l[1] = *(const uint32_t*)(ql + qb + (size_t)(gid + 8) * 512 + d);
        a_l[2] = *(const uint32_t*)(ql + qb + (size_t)gid * 512 + d + 8);
        a_l[3] = *(const uint32_t*)(ql + qb + (size_t)(gid + 8) * 512 + d + 8);
        #pragma unroll
        for (int nf = 0; nf < 8; nf++) {
            const size_t ko = kvb + (size_t)(nf * 8 + gid) * 1024 + d;
            uint32_t b_h[2] = { *(const uint32_t*)(kvh + ko), *(const uint32_t*)(kvh + ko + 8) };
            uint32_t b_l[2] = { *(const uint32_t*)(kvl + ko), *(const uint32_t*)(kvl + ko + 8) };
            mma16(s[nf], a_h, b_h);
            mma16(s[nf], a_l, b_h);
            mma16(s[nf], a_h, b_l);
        }
    }

    // ---- scale + mask ----
    #pragma unroll
    for (int nf = 0; nf < 8; nf++)
        #pragma unroll
        for (int j = 0; j < 4; j++) {
            int row = gid + (j >> 1) * 8;
            int e = nf * 8 + 2 * tig + (j & 1);
            float v = s[nf][j] * 0.125f;
            if (ms[row * 64 + e] != 0u) v = -1e30f;
            s[nf][j] = v;
        }

    // ---- softmax over e (rows gid, gid+8 live in quad tig) ----
    float mx0 = -3e38f, mx1 = -3e38f;
    #pragma unroll
    for (int nf = 0; nf < 8; nf++) {
        mx0 = fmaxf(mx0, fmaxf(s[nf][0], s[nf][1]));
        mx1 = fmaxf(mx1, fmaxf(s[nf][2], s[nf][3]));
    }
    mx0 = fmaxf(mx0, __shfl_xor_sync(0xffffffffu, mx0, 1));
    mx0 = fmaxf(mx0, __shfl_xor_sync(0xffffffffu, mx0, 2));
    mx1 = fmaxf(mx1, __shfl_xor_sync(0xffffffffu, mx1, 1));
    mx1 = fmaxf(mx1, __shfl_xor_sync(0xffffffffu, mx1, 2));
    float sm0 = 0.f, sm1 = 0.f;
    #pragma unroll
    for (int nf = 0; nf < 8; nf++) {
        s[nf][0] = __expf(s[nf][0] - mx0);
        s[nf][1] = __expf(s[nf][1] - mx0);
        s[nf][2] = __expf(s[nf][2] - mx1);
        s[nf][3] = __expf(s[nf][3] - mx1);
        sm0 += s[nf][0] + s[nf][1];
        sm1 += s[nf][2] + s[nf][3];
    }
    sm0 += __shfl_xor_sync(0xffffffffu, sm0, 1);
    sm0 += __shfl_xor_sync(0xffffffffu, sm0, 2);
    sm1 += __shfl_xor_sync(0xffffffffu, sm1, 1);
    sm1 += __shfl_xor_sync(0xffffffffu, sm1, 2);
    const float inv0 = (mx0 <= -1e29f) ? 0.f : (1.f / sm0);
    const float inv1 = (mx1 <= -1e29f) ? 0.f : (1.f / sm1);

    // ---- W fragments (hi/lo fp16): identity S-frag -> A-frag relayout ----
    uint32_t wh01[8], wh23[8], wl01[8], wl23[8];
    #pragma unroll
    for (int nf = 0; nf < 8; nf++) {
        float w0 = s[nf][0] * inv0, w1 = s[nf][1] * inv0;
        float w2 = s[nf][2] * inv1, w3 = s[nf][3] * inv1;
        half2 h01 = __floats2half2_rn(w0, w1);
        half2 h23 = __floats2half2_rn(w2, w3);
        float2 f01 = __half22float2(h01), f23 = __half22float2(h23);
        half2 l01 = __floats2half2_rn(w0 - f01.x, w1 - f01.y);
        half2 l23 = __floats2half2_rn(w2 - f23.x, w3 - f23.y);
        wh01[nf] = *(uint32_t*)&h01; wh23[nf] = *(uint32_t*)&h23;
        wl01[nf] = *(uint32_t*)&l01; wl23[nf] = *(uint32_t*)&l23;
    }

    // ---- O = W V ----
    float o[8][4];
    #pragma unroll
    for (int nf = 0; nf < 8; nf++)
        #pragma unroll
        for (int j = 0; j < 4; j++) o[nf][j] = 0.f;

    #pragma unroll
    for (int t = 0; t < 4; t++) {
        uint32_t a_h[4] = { wh01[2 * t], wh23[2 * t], wh01[2 * t + 1], wh23[2 * t + 1] };
        uint32_t a_l[4] = { wl01[2 * t], wl23[2 * t], wl01[2 * t + 1], wl23[2 * t + 1] };
        const int e0 = t * 16 + 2 * tig;
        #pragma unroll
        for (int nf = 0; nf < 8; nf++) {
            const int d = nf * 8 + gid;
            const __half* ph = kvh + kvb + 512 + (size_t)e0 * 1024 + d;
            const __half* pl = kvl + kvb + 512 + (size_t)e0 * 1024 + d;
            half2 bh0 = __halves2half2(ph[0],        ph[1024]);
            half2 bh1 = __halves2half2(ph[8 * 1024], ph[9 * 1024]);
            half2 bl0 = __halves2half2(pl[0],        pl[1024]);
            half2 bl1 = __halves2half2(pl[8 * 1024], pl[9 * 1024]);
            uint32_t b_h[2] = { *(uint32_t*)&bh0, *(uint32_t*)&bh1 };
            uint32_t b_l[2] = { *(uint32_t*)&bl0, *(uint32_t*)&bl1 };
            mma16(o[nf], a_h, b_h);
            mma16(o[nf], a_l, b_h);
            mma16(o[nf], a_h, b_l);
        }
    }

    // ---- store O split hi/lo ----
    #pragma unroll
    for (int nf = 0; nf < 8; nf++) {
        const int col = nf * 8 + 2 * tig;
        half2 h01 = __floats2half2_rn(o[nf][0], o[nf][1]);
        half2 h23 = __floats2half2_rn(o[nf][2], o[nf][3]);
        float2 f01 = __half22float2(h01), f23 = __half22float2(h23);
        half2 l01 = __floats2half2_rn(o[nf][0] - f01.x, o[nf][1] - f01.y);
        half2 l23 = __floats2half2_rn(o[nf][2] - f23.x, o[nf][3] - f23.y);
        *(uint32_t*)(ath + qb + (size_t)gid * 512 + col)       = *(uint32_t*)&h01;
        *(uint32_t*)(atl + qb + (size_t)gid * 512 + col)       = *(uint32_t*)&l01;
        *(uint32_t*)(ath + qb + (size_t)(gid + 8) * 512 + col) = *(uint32_t*)&h23;
        *(uint32_t*)(atl + qb + (size_t)(gid + 8) * 512 + col) = *(uint32_t*)&l23;
    }
}

// ---------------------------------------------------------------------------
extern "C" void kernel_launch(void* const* d_in, const int* in_sizes, int n_in,
                              void* d_out, int out_size)
{
    (void)in_sizes; (void)n_in; (void)out_size;
    const float*    entities    = (const float*)d_in[0];
    const unsigned* obs_mask    = (const unsigned*)d_in[1];
    const unsigned* entity_mask = (const unsigned*)d_in[2];
    const float*    W1    = (const float*)d_in[3];
    const float*    b1    = (const float*)d_in[4];
    const float*    Win   = (const float*)d_in[5];
    const float*    Wout  = (const float*)d_in[6];
    const float*    b_out = (const float*)d_in[7];
    const float*    W2    = (const float*)d_in[8];
    const float*    b2    = (const float*)d_in[9];
    float* out = (float*)d_out;

    __half *enth, *entl, *x1h, *x1l, *kvh, *kvl, *qh, *ql, *ath, *atl, *hh, *hl;
    __half *w1h, *w1l, *winh, *winl, *woh, *wol, *w2h, *w2l;
    cudaGetSymbolAddress((void**)&enth, g_enth); cudaGetSymbolAddress((void**)&entl, g_entl);
    cudaGetSymbolAddress((void**)&x1h,  g_x1h);  cudaGetSymbolAddress((void**)&x1l,  g_x1l);
    cudaGetSymbolAddress((void**)&kvh,  g_kvh);  cudaGetSymbolAddress((void**)&kvl,  g_kvl);
    cudaGetSymbolAddress((void**)&qh,   g_qh);   cudaGetSymbolAddress((void**)&ql,   g_ql);
    cudaGetSymbolAddress((void**)&ath,  g_ath);  cudaGetSymbolAddress((void**)&atl,  g_atl);
    cudaGetSymbolAddress((void**)&hh,   g_hh);   cudaGetSymbolAddress((void**)&hl,   g_hl);
    cudaGetSymbolAddress((void**)&w1h,  g_W1h);  cudaGetSymbolAddress((void**)&w1l,  g_W1l);
    cudaGetSymbolAddress((void**)&winh, g_Winh); cudaGetSymbolAddress((void**)&winl, g_Winl);
    cudaGetSymbolAddress((void**)&woh,  g_Woh);  cudaGetSymbolAddress((void**)&wol,  g_Wol);
    cudaGetSymbolAddress((void**)&w2h,  g_W2h);  cudaGetSymbolAddress((void**)&w2l,  g_W2l);

    cudaFuncSetAttribute(gemm_v2, cudaFuncAttributeMaxDynamicSharedMemorySize, GSMEM);

    auto split = [&](const float* src, __half* hi, __half* lo, size_t n) {
        int n4 = (int)(n / 4);
        split_kernel<<<(n4 + 255) / 256, 256>>>(
            (const float4*)src, (uint2*)hi, (uint2*)lo, n4);
    };
    split(entities, enth, entl, (size_t)M_X1 * 128);
    split(W1,   w1h,  w1l,  (size_t)512 * 128);
    split(Win,  winh, winl, (size_t)1536 * 512);
    split(Wout, woh,  wol,  (size_t)512 * 512);
    split(W2,   w2h,  w2l,  (size_t)512 * 512);

    // 1) x1 = relu(entities @ W1^T + b1)   [131072,512], K=128
    gemm_v2<<<dim3(4, 1024), 256, GSMEM>>>(
        enth, entl, w1h, w1l, x1h, x1l, nullptr,
        M_X1, 512, 128, b1, nullptr, 1);

    // 2) kv = x1 @ Win[512:1536]^T         [131072,1024], K=512
    gemm_v2<<<dim3(8, 1024), 256, GSMEM>>>(
        x1h, x1l, winh + (size_t)512 * 512, winl + (size_t)512 * 512, kvh, kvl, nullptr,
        M_X1, 1024, 512, nullptr, nullptr, 0);

    // 3) q = x1[agents] @ Win[0:512]^T     [32768,512], K=512
    gemm_v2<<<dim3(4, 256), 256, GSMEM>>>(
        x1h, x1l, winh, winl, qh, ql, nullptr,
        M_AG, 512, 512, nullptr, nullptr, 4);

    // 4) masked multi-head attention (MMA, block per bt)
    attn_mma<<<BT_, 256>>>(qh, ql, kvh, kvl, obs_mask, ath, atl);

    // 5) h = mask0(relu(attn @ Wout^T + b_out))
    gemm_v2<<<dim3(4, 256), 256, GSMEM>>>(
        ath, atl, woh, wol, hh, hl, nullptr,
        M_AG, 512, 512, b_out, entity_mask, 3);

    // 6) out = relu(h @ W2^T + b2) -> fp32
    gemm_v2<<<dim3(4, 256), 256, GSMEM>>>(
        hh, hl, w2h, w2l, nullptr, nullptr, out,
        M_AG, 512, 512, b2, nullptr, 1 | 8);
}

// round 7
// speedup vs baseline: 2.2921x; 1.0016x over previous
#include <cuda_runtime.h>
#include <cuda_fp16.h>
#include <cstdint>
#include <cstddef>

// B=32,T=64 -> BT=2048; NE=64; NA=16; ED=128; E=512; H=8; HD=64; R=512
#define BT_   2048
#define M_X1  131072
#define M_AG  32768

// ---------------------------------------------------------------------------
// fp16 hi/lo split operand storage (device globals; allocation forbidden)
// ---------------------------------------------------------------------------
__device__ __half g_enth[(size_t)M_X1 * 128], g_entl[(size_t)M_X1 * 128];
__device__ __half g_x1h [(size_t)M_X1 * 512], g_x1l [(size_t)M_X1 * 512];
__device__ __half g_kvh [(size_t)M_X1 * 1024], g_kvl[(size_t)M_X1 * 1024];
__device__ __half g_ath [(size_t)M_AG * 512], g_atl [(size_t)M_AG * 512];
__device__ __half g_hh  [(size_t)M_AG * 512], g_hl  [(size_t)M_AG * 512];
__device__ __half g_qh  [(size_t)M_AG * 512], g_ql  [(size_t)M_AG * 512];
__device__ __half g_W1h [512 * 128],  g_W1l [512 * 128];
__device__ __half g_Winh[1536 * 512], g_Winl[1536 * 512];
__device__ __half g_Woh [512 * 512],  g_Wol [512 * 512];
__device__ __half g_W2h [512 * 512],  g_W2l [512 * 512];

// ---------------------------------------------------------------------------
__device__ __forceinline__ uint32_t smem_u32(const void* p) {
    uint32_t a;
    asm("{ .reg .u64 t; cvta.to.shared.u64 t, %1; cvt.u32.u64 %0, t; }" : "=r"(a) : "l"(p));
    return a;
}

#define LDSM4(r, a) \
    asm volatile("ldmatrix.sync.aligned.m8n8.x4.shared.b16 {%0,%1,%2,%3}, [%4];" \
        : "=r"((r)[0]), "=r"((r)[1]), "=r"((r)[2]), "=r"((r)[3]) : "r"(a))

#define CP16(d, s)  asm volatile("cp.async.cg.shared.global [%0], [%1], 16;" :: "r"(d), "l"(s))
#define CPCOMMIT()  asm volatile("cp.async.commit_group;" ::: "memory")
#define CPWAIT1()   asm volatile("cp.async.wait_group 1;" ::: "memory")

__device__ __forceinline__ void mma16(float* d, const uint32_t* a, const uint32_t* b) {
    asm volatile(
        "mma.sync.aligned.m16n8k16.row.col.f32.f16.f16.f32 "
        "{%0,%1,%2,%3},{%4,%5,%6,%7},{%8,%9},{%0,%1,%2,%3};\n"
        : "+f"(d[0]), "+f"(d[1]), "+f"(d[2]), "+f"(d[3])
        : "r"(a[0]), "r"(a[1]), "r"(a[2]), "r"(a[3]), "r"(b[0]), "r"(b[1]));
}

// ---------------------------------------------------------------------------
// split kernel: fp32 -> fp16 hi + fp16 lo residual (elementwise, vec4)
// ---------------------------------------------------------------------------
__global__ void split_kernel(const float4* __restrict__ x,
                             uint2* __restrict__ hi, uint2* __restrict__ lo, int n4)
{
    int i = blockIdx.x * blockDim.x + threadIdx.x;
    if (i >= n4) return;
    float4 v = x[i];
    half2 h0 = __floats2half2_rn(v.x, v.y);
    half2 h1 = __floats2half2_rn(v.z, v.w);
    float2 f0 = __half22float2(h0), f1 = __half22float2(h1);
    half2 l0 = __floats2half2_rn(v.x - f0.x, v.y - f0.y);
    half2 l1 = __floats2half2_rn(v.z - f1.x, v.w - f1.y);
    hi[i] = make_uint2(*(uint32_t*)&h0, *(uint32_t*)&h1);
    lo[i] = make_uint2(*(uint32_t*)&l0, *(uint32_t*)&l1);
}

// ---------------------------------------------------------------------------
// fp16x3 NT GEMM (unchanged from R5 — at legacy-HMMA rate ceiling)
// ---------------------------------------------------------------------------
#define ROWB 80
#define OAH  0
#define OAL  10240
#define OBH  20480
#define OBL  30720
#define BUFB 40960
#define GSMEM (2 * BUFB)

__global__ __launch_bounds__(256, 2) void gemm_v2(
    const __half* __restrict__ Ah, const __half* __restrict__ Al,
    const __half* __restrict__ Bh, const __half* __restrict__ Bl,
    __half* __restrict__ Ch, __half* __restrict__ Cl, float* __restrict__ Cf,
    int M, int N, int K,
    const float* __restrict__ bias, const unsigned* __restrict__ emask, int flags)
{
    extern __shared__ char sm_[];
    const uint32_t sb = smem_u32(sm_);
    const int tid = threadIdx.x, lane = tid & 31, warp = tid >> 5;
    const int wm = warp >> 1, wn = warp & 1;
    const int bm = blockIdx.y * 128, bn = blockIdx.x * 128;
    const int CCH = K >> 5;

    const int srow = tid >> 2, sseg = tid & 3;
    size_t aoff[2], boff[2];
    #pragma unroll
    for (int p = 0; p < 2; p++) {
        int grow = bm + srow + 64 * p;
        int arow = (flags & 4) ? ((grow >> 4) * 64 + (grow & 15)) : grow;
        aoff[p] = (size_t)arow * K + sseg * 8;
        boff[p] = (size_t)(bn + srow + 64 * p) * K + sseg * 8;
    }
    const uint32_t sdst = (uint32_t)(srow * ROWB + sseg * 16);

    #define STAGE(c) do {                                               \
        uint32_t base_ = sb + ((c) & 1) * BUFB;                          \
        int k0_ = (c) << 5;                                              \
        _Pragma("unroll")                                                \
        for (int p_ = 0; p_ < 2; p_++) {                                 \
            uint32_t d_ = base_ + sdst + p_ * 64 * ROWB;                 \
            CP16(d_ + OAH, Ah + aoff[p_] + k0_);                         \
            CP16(d_ + OAL, Al + aoff[p_] + k0_);                         \
            CP16(d_ + OBH, Bh + boff[p_] + k0_);                         \
            CP16(d_ + OBL, Bl + boff[p_] + k0_);                         \
        }                                                                \
    } while (0)

    float acc[2][8][4];
    #pragma unroll
    for (int i = 0; i < 2; i++)
        #pragma unroll
        for (int j = 0; j < 8; j++)
            #pragma unroll
            for (int t = 0; t < 4; t++) acc[i][j][t] = 0.f;

    const uint32_t aOff = (uint32_t)((wm * 32 + (lane & 15)) * ROWB + (lane >> 4) * 16);
    const uint32_t bOff = (uint32_t)((wn * 64 + lane) * ROWB);

    STAGE(0); CPCOMMIT();
    STAGE(1); CPCOMMIT();

    for (int c = 0; c < CCH; c++) {
        CPWAIT1();
        __syncthreads();
        const uint32_t base = sb + (c & 1) * BUFB;

        #pragma unroll
        for (int step = 0; step < 2; step++) {
            uint32_t ah[2][4], alr[2][4], b[8][2], r[4];
            #pragma unroll
            for (int mf = 0; mf < 2; mf++)
                LDSM4(ah[mf], base + OAH + aOff + mf * 16 * ROWB + step * 32);
            #pragma unroll
            for (int q = 0; q < 2; q++)
                #pragma unroll
                for (int kh = 0; kh < 2; kh++) {
                    LDSM4(r, base + OBH + bOff + q * 32 * ROWB + step * 32 + kh * 16);
                    b[q * 4 + 0][kh] = r[0]; b[q * 4 + 1][kh] = r[1];
                    b[q * 4 + 2][kh] = r[2]; b[q * 4 + 3][kh] = r[3];
                }
            #pragma unroll
            for (int nf = 0; nf < 8; nf++)
                #pragma unroll
                for (int mf = 0; mf < 2; mf++)
                    mma16(acc[mf][nf], ah[mf], b[nf]);
            #pragma unroll
            for (int mf = 0; mf < 2; mf++)
                LDSM4(alr[mf], base + OAL + aOff + mf * 16 * ROWB + step * 32);
            #pragma unroll
            for (int nf = 0; nf < 8; nf++)
                #pragma unroll
                for (int mf = 0; mf < 2; mf++)
                    mma16(acc[mf][nf], alr[mf], b[nf]);
            #pragma unroll
            for (int q = 0; q < 2; q++)
                #pragma unroll
                for (int kh = 0; kh < 2; kh++) {
                    LDSM4(r, base + OBL + bOff + q * 32 * ROWB + step * 32 + kh * 16);
                    b[q * 4 + 0][kh] = r[0]; b[q * 4 + 1][kh] = r[1];
                    b[q * 4 + 2][kh] = r[2]; b[q * 4 + 3][kh] = r[3];
                }
            #pragma unroll
            for (int nf = 0; nf < 8; nf++)
                #pragma unroll
                for (int mf = 0; mf < 2; mf++)
                    mma16(acc[mf][nf], ah[mf], b[nf]);
        }
        __syncthreads();
        if (c + 2 < CCH) STAGE(c + 2);
        CPCOMMIT();
    }
    #undef STAGE

    const int gid = lane >> 2, tig = lane & 3;
    #pragma unroll
    for (int mf = 0; mf < 2; mf++) {
        int r0 = bm + wm * 32 + mf * 16 + gid;
        bool z0 = false, z1 = false;
        if (flags & 2) {
            int e0 = ((r0    ) >> 4) * 64 + ((r0    ) & 15);
            int e1 = ((r0 + 8) >> 4) * 64 + ((r0 + 8) & 15);
            z0 = (emask[e0] != 0u);
            z1 = (emask[e1] != 0u);
        }
        #pragma unroll
        for (int nf = 0; nf < 8; nf++) {
            int c = bn + wn * 64 + nf * 8 + tig * 2;
            float b0 = bias ? bias[c] : 0.f;
            float b1 = bias ? bias[c + 1] : 0.f;
            float v0 = acc[mf][nf][0] + b0;
            float v1 = acc[mf][nf][1] + b1;
            float v2 = acc[mf][nf][2] + b0;
            float v3 = acc[mf][nf][3] + b1;
            if (flags & 1) {
                v0 = fmaxf(v0, 0.f); v1 = fmaxf(v1, 0.f);
                v2 = fmaxf(v2, 0.f); v3 = fmaxf(v3, 0.f);
            }
            if (z0) { v0 = 0.f; v1 = 0.f; }
            if (z1) { v2 = 0.f; v3 = 0.f; }
            if (flags & 8) {
                *(float2*)(Cf + (size_t)r0 * N + c)       = make_float2(v0, v1);
                *(float2*)(Cf + (size_t)(r0 + 8) * N + c) = make_float2(v2, v3);
            } else {
                half2 h01 = __floats2half2_rn(v0, v1);
                half2 h23 = __floats2half2_rn(v2, v3);
                float2 f01 = __half22float2(h01), f23 = __half22float2(h23);
                half2 l01 = __floats2half2_rn(v0 - f01.x, v1 - f01.y);
                half2 l23 = __floats2half2_rn(v2 - f23.x, v3 - f23.y);
                *(uint32_t*)(Ch + (size_t)r0 * N + c)       = *(uint32_t*)&h01;
                *(uint32_t*)(Cl + (size_t)r0 * N + c)       = *(uint32_t*)&l01;
                *(uint32_t*)(Ch + (size_t)(r0 + 8) * N + c) = *(uint32_t*)&h23;
                *(uint32_t*)(Cl + (size_t)(r0 + 8) * N + c) = *(uint32_t*)&l23;
            }
        }
    }
}

// ---------------------------------------------------------------------------
// MMA attention: block per bt (256 thr), warp = head.
// S = (Q·K^T)/8 masked, softmax in-fragment, O = W·V. fp16x3/x2.5 split math.
// Fragments loaded straight from gmem (q/k contiguous u32 pairs; V scalar).
// ---------------------------------------------------------------------------
__global__ __launch_bounds__(256) void attn_mma(
    const __half* __restrict__ qh, const __half* __restrict__ ql,
    const __half* __restrict__ kvh, const __half* __restrict__ kvl,
    const unsigned* __restrict__ obs,
    __half* __restrict__ ath, __half* __restrict__ atl)
{
    const int bt = blockIdx.x;
    const int h = threadIdx.x >> 5;
    const int lane = threadIdx.x & 31;
    const int gid = lane >> 2, tig = lane & 3;

    __shared__ unsigned ms[1024];     // obs[bt] : 16 x 64
    #pragma unroll
    for (int i = 0; i < 4; i++) ms[threadIdx.x + 256 * i] = obs[(size_t)bt * 4096 + threadIdx.x + 256 * i];
    __syncthreads();

    const size_t qb  = (size_t)(bt * 16) * 512 + h * 64;
    const size_t kvb = (size_t)(bt * 64) * 1024 + h * 64;

    // ---- S = Q K^T ----
    float s[8][4];
    #pragma unroll
    for (int nf = 0; nf < 8; nf++)
        #pragma unroll
        for (int j = 0; j < 4; j++) s[nf][j] = 0.f;

    #pragma unroll
    for (int t = 0; t < 4; t++) {
        const int d = t * 16 + 2 * tig;
        uint32_t a_h[4], a_l[4];
        a_h[0] = *(const uint32_t*)(qh + qb + (size_t)gid * 512 + d);
        a_h[1] = *(const uint32_t*)(qh + qb + (size_t)(gid + 8) * 512 + d);
        a_h[2] = *(const uint32_t*)(qh + qb + (size_t)gid * 512 + d + 8);
        a_h[3] = *(const uint32_t*)(qh + qb + (size_t)(gid + 8) * 512 + d + 8);
        a_l[0] = *(const uint32_t*)(ql + qb + (size_t)gid * 512 + d);
        a_l[1] = *(const uint32_t*)(ql + qb + (size_t)(gid + 8) * 512 + d);
        a_l[2] = *(const uint32_t*)(ql + qb + (size_t)gid * 512 + d + 8);
        a_l[3] = *(const uint32_t*)(ql + qb + (size_t)(gid + 8) * 512 + d + 8);
        #pragma unroll
        for (int nf = 0; nf < 8; nf++) {
            const size_t ko = kvb + (size_t)(nf * 8 + gid) * 1024 + d;
            uint32_t b_h[2] = { *(const uint32_t*)(kvh + ko), *(const uint32_t*)(kvh + ko + 8) };
            uint32_t b_l[2] = { *(const uint32_t*)(kvl + ko), *(const uint32_t*)(kvl + ko + 8) };
            mma16(s[nf], a_h, b_h);
            mma16(s[nf], a_l, b_h);
            mma16(s[nf], a_h, b_l);
        }
    }

    // ---- scale + mask ----
    #pragma unroll
    for (int nf = 0; nf < 8; nf++)
        #pragma unroll
        for (int j = 0; j < 4; j++) {
            int row = gid + (j >> 1) * 8;
            int e = nf * 8 + 2 * tig + (j & 1);
            float v = s[nf][j] * 0.125f;
            if (ms[row * 64 + e] != 0u) v = -1e30f;
            s[nf][j] = v;
        }

    // ---- softmax over e (rows gid, gid+8 live in quad tig) ----
    float mx0 = -3e38f, mx1 = -3e38f;
    #pragma unroll
    for (int nf = 0; nf < 8; nf++) {
        mx0 = fmaxf(mx0, fmaxf(s[nf][0], s[nf][1]));
        mx1 = fmaxf(mx1, fmaxf(s[nf][2], s[nf][3]));
    }
    mx0 = fmaxf(mx0, __shfl_xor_sync(0xffffffffu, mx0, 1));
    mx0 = fmaxf(mx0, __shfl_xor_sync(0xffffffffu, mx0, 2));
    mx1 = fmaxf(mx1, __shfl_xor_sync(0xffffffffu, mx1, 1));
    mx1 = fmaxf(mx1, __shfl_xor_sync(0xffffffffu, mx1, 2));
    float sm0 = 0.f, sm1 = 0.f;
    #pragma unroll
    for (int nf = 0; nf < 8; nf++) {
        s[nf][0] = __expf(s[nf][0] - mx0);
        s[nf][1] = __expf(s[nf][1] - mx0);
        s[nf][2] = __expf(s[nf][2] - mx1);
        s[nf][3] = __expf(s[nf][3] - mx1);
        sm0 += s[nf][0] + s[nf][1];
        sm1 += s[nf][2] + s[nf][3];
    }
    sm0 += __shfl_xor_sync(0xffffffffu, sm0, 1);
    sm0 += __shfl_xor_sync(0xffffffffu, sm0, 2);
    sm1 += __shfl_xor_sync(0xffffffffu, sm1, 1);
    sm1 += __shfl_xor_sync(0xffffffffu, sm1, 2);
    const float inv0 = (mx0 <= -1e29f) ? 0.f : (1.f / sm0);
    const float inv1 = (mx1 <= -1e29f) ? 0.f : (1.f / sm1);

    // ---- W fragments (hi/lo fp16): identity S-frag -> A-frag relayout ----
    uint32_t wh01[8], wh23[8], wl01[8], wl23[8];
    #pragma unroll
    for (int nf = 0; nf < 8; nf++) {
        float w0 = s[nf][0] * inv0, w1 = s[nf][1] * inv0;
        float w2 = s[nf][2] * inv1, w3 = s[nf][3] * inv1;
        half2 h01 = __floats2half2_rn(w0, w1);
        half2 h23 = __floats2half2_rn(w2, w3);
        float2 f01 = __half22float2(h01), f23 = __half22float2(h23);
        half2 l01 = __floats2half2_rn(w0 - f01.x, w1 - f01.y);
        half2 l23 = __floats2half2_rn(w2 - f23.x, w3 - f23.y);
        wh01[nf] = *(uint32_t*)&h01; wh23[nf] = *(uint32_t*)&h23;
        wl01[nf] = *(uint32_t*)&l01; wl23[nf] = *(uint32_t*)&l23;
    }

    // ---- O = W V ----
    float o[8][4];
    #pragma unroll
    for (int nf = 0; nf < 8; nf++)
        #pragma unroll
        for (int j = 0; j < 4; j++) o[nf][j] = 0.f;

    #pragma unroll
    for (int t = 0; t < 4; t++) {
        uint32_t a_h[4] = { wh01[2 * t], wh23[2 * t], wh01[2 * t + 1], wh23[2 * t + 1] };
        uint32_t a_l[4] = { wl01[2 * t], wl23[2 * t], wl01[2 * t + 1], wl23[2 * t + 1] };
        const int e0 = t * 16 + 2 * tig;
        #pragma unroll
        for (int nf = 0; nf < 8; nf++) {
            const int d = nf * 8 + gid;
            const __half* ph = kvh + kvb + 512 + (size_t)e0 * 1024 + d;
            const __half* pl = kvl + kvb + 512 + (size_t)e0 * 1024 + d;
            half2 bh0 = __halves2half2(ph[0],        ph[1024]);
            half2 bh1 = __halves2half2(ph[8 * 1024], ph[9 * 1024]);
            half2 bl0 = __halves2half2(pl[0],        pl[1024]);
            half2 bl1 = __halves2half2(pl[8 * 1024], pl[9 * 1024]);
            uint32_t b_h[2] = { *(uint32_t*)&bh0, *(uint32_t*)&bh1 };
            uint32_t b_l[2] = { *(uint32_t*)&bl0, *(uint32_t*)&bl1 };
            mma16(o[nf], a_h, b_h);
            mma16(o[nf], a_l, b_h);
            mma16(o[nf], a_h, b_l);
        }
    }

    // ---- store O split hi/lo ----
    #pragma unroll
    for (int nf = 0; nf < 8; nf++) {
        const int col = nf * 8 + 2 * tig;
        half2 h01 = __floats2half2_rn(o[nf][0], o[nf][1]);
        half2 h23 = __floats2half2_rn(o[nf][2], o[nf][3]);
        float2 f01 = __half22float2(h01), f23 = __half22float2(h23);
        half2 l01 = __floats2half2_rn(o[nf][0] - f01.x, o[nf][1] - f01.y);
        half2 l23 = __floats2half2_rn(o[nf][2] - f23.x, o[nf][3] - f23.y);
        *(uint32_t*)(ath + qb + (size_t)gid * 512 + col)       = *(uint32_t*)&h01;
        *(uint32_t*)(atl + qb + (size_t)gid * 512 + col)       = *(uint32_t*)&l01;
        *(uint32_t*)(ath + qb + (size_t)(gid + 8) * 512 + col) = *(uint32_t*)&h23;
        *(uint32_t*)(atl + qb + (size_t)(gid + 8) * 512 + col) = *(uint32_t*)&l23;
    }
}

// ---------------------------------------------------------------------------
extern "C" void kernel_launch(void* const* d_in, const int* in_sizes, int n_in,
                              void* d_out, int out_size)
{
    (void)in_sizes; (void)n_in; (void)out_size;
    const float*    entities    = (const float*)d_in[0];
    const unsigned* obs_mask    = (const unsigned*)d_in[1];
    const unsigned* entity_mask = (const unsigned*)d_in[2];
    const float*    W1    = (const float*)d_in[3];
    const float*    b1    = (const float*)d_in[4];
    const float*    Win   = (const float*)d_in[5];
    const float*    Wout  = (const float*)d_in[6];
    const float*    b_out = (const float*)d_in[7];
    const float*    W2    = (const float*)d_in[8];
    const float*    b2    = (const float*)d_in[9];
    float* out = (float*)d_out;

    __half *enth, *entl, *x1h, *x1l, *kvh, *kvl, *qh, *ql, *ath, *atl, *hh, *hl;
    __half *w1h, *w1l, *winh, *winl, *woh, *wol, *w2h, *w2l;
    cudaGetSymbolAddress((void**)&enth, g_enth); cudaGetSymbolAddress((void**)&entl, g_entl);
    cudaGetSymbolAddress((void**)&x1h,  g_x1h);  cudaGetSymbolAddress((void**)&x1l,  g_x1l);
    cudaGetSymbolAddress((void**)&kvh,  g_kvh);  cudaGetSymbolAddress((void**)&kvl,  g_kvl);
    cudaGetSymbolAddress((void**)&qh,   g_qh);   cudaGetSymbolAddress((void**)&ql,   g_ql);
    cudaGetSymbolAddress((void**)&ath,  g_ath);  cudaGetSymbolAddress((void**)&atl,  g_atl);
    cudaGetSymbolAddress((void**)&hh,   g_hh);   cudaGetSymbolAddress((void**)&hl,   g_hl);
    cudaGetSymbolAddress((void**)&w1h,  g_W1h);  cudaGetSymbolAddress((void**)&w1l,  g_W1l);
    cudaGetSymbolAddress((void**)&winh, g_Winh); cudaGetSymbolAddress((void**)&winl, g_Winl);
    cudaGetSymbolAddress((void**)&woh,  g_Woh);  cudaGetSymbolAddress((void**)&wol,  g_Wol);
    cudaGetSymbolAddress((void**)&w2h,  g_W2h);  cudaGetSymbolAddress((void**)&w2l,  g_W2l);

    cudaFuncSetAttribute(gemm_v2, cudaFuncAttributeMaxDynamicSharedMemorySize, GSMEM);

    auto split = [&](const float* src, __half* hi, __half* lo, size_t n) {
        int n4 = (int)(n / 4);
        split_kernel<<<(n4 + 255) / 256, 256>>>(
            (const float4*)src, (uint2*)hi, (uint2*)lo, n4);
    };
    split(entities, enth, entl, (size_t)M_X1 * 128);
    split(W1,   w1h,  w1l,  (size_t)512 * 128);
    split(Win,  winh, winl, (size_t)1536 * 512);
    split(Wout, woh,  wol,  (size_t)512 * 512);
    split(W2,   w2h,  w2l,  (size_t)512 * 512);

    // 1) x1 = relu(entities @ W1^T + b1)   [131072,512], K=128
    gemm_v2<<<dim3(4, 1024), 256, GSMEM>>>(
        enth, entl, w1h, w1l, x1h, x1l, nullptr,
        M_X1, 512, 128, b1, nullptr, 1);

    // 2) kv = x1 @ Win[512:1536]^T         [131072,1024], K=512
    gemm_v2<<<dim3(8, 1024), 256, GSMEM>>>(
        x1h, x1l, winh + (size_t)512 * 512, winl + (size_t)512 * 512, kvh, kvl, nullptr,
        M_X1, 1024, 512, nullptr, nullptr, 0);

    // 3) q = x1[agents] @ Win[0:512]^T     [32768,512], K=512
    gemm_v2<<<dim3(4, 256), 256, GSMEM>>>(
        x1h, x1l, winh, winl, qh, ql, nullptr,
        M_AG, 512, 512, nullptr, nullptr, 4);

    // 4) masked multi-head attention (MMA, block per bt)
    attn_mma<<<BT_, 256>>>(qh, ql, kvh, kvl, obs_mask, ath, atl);

    // 5) h = mask0(relu(attn @ Wout^T + b_out))
    gemm_v2<<<dim3(4, 256), 256, GSMEM>>>(
        ath, atl, woh, wol, hh, hl, nullptr,
        M_AG, 512, 512, b_out, entity_mask, 3);

    // 6) out = relu(h @ W2^T + b2) -> fp32
    gemm_v2<<<dim3(4, 256), 256, GSMEM>>>(
        hh, hl, w2h, w2l, nullptr, nullptr, out,
        M_AG, 512, 512, b2, nullptr, 1 | 8);
}